// round 2
// baseline (speedup 1.0000x reference)
#include <cuda_runtime.h>
#include <cstdint>

#define T_TOK 4096
#define HID   1024
#define INTER 4096
#define NEXP  8

#define BM 128
#define BN 128
#define BK 16

// Scratch: h = gelu(x @ W1_e + b1_e) for the current expert, fp32 [T, I].
__device__ float g_h[(size_t)T_TOK * (size_t)INTER];
// Gate scores after softmax, [T, E].
__device__ float g_gate[T_TOK * NEXP];

// ---------------------------------------------------------------------------
// Packed f32x2 helpers (B300 doubles fp32 FMA throughput via fma.rn.f32x2)
// ---------------------------------------------------------------------------
__device__ __forceinline__ unsigned long long pack2(float lo, float hi) {
    unsigned long long r;
    asm("mov.b64 %0, {%1, %2};" : "=l"(r) : "f"(lo), "f"(hi));
    return r;
}
__device__ __forceinline__ void fma2(unsigned long long& d,
                                     unsigned long long a,
                                     unsigned long long b) {
    asm("fma.rn.f32x2 %0, %1, %2, %0;" : "+l"(d) : "l"(a), "l"(b));
}
__device__ __forceinline__ float2 unpack2(unsigned long long v) {
    float2 f;
    asm("mov.b64 {%0, %1}, %2;" : "=f"(f.x), "=f"(f.y) : "l"(v));
    return f;
}

__device__ __forceinline__ float gelu_exact(float v) {
    // jax.nn.gelu(approximate=False) = v * Phi(v)
    return v * normcdff(v);
}

// ---------------------------------------------------------------------------
// Gate: logits = x @ Wg^T, softmax over E=8. One warp per token.
// ---------------------------------------------------------------------------
__global__ void gate_kernel(const float* __restrict__ x,
                            const float* __restrict__ Wg,
                            float* __restrict__ gate) {
    int warp = (blockIdx.x * blockDim.x + threadIdx.x) >> 5;
    int lane = threadIdx.x & 31;
    if (warp >= T_TOK) return;
    const float* xr = x + (size_t)warp * HID;

    float acc[NEXP];
#pragma unroll
    for (int e = 0; e < NEXP; e++) acc[e] = 0.f;

    for (int k = lane; k < HID; k += 32) {
        float xv = xr[k];
#pragma unroll
        for (int e = 0; e < NEXP; e++) acc[e] = fmaf(xv, Wg[e * HID + k], acc[e]);
    }
#pragma unroll
    for (int e = 0; e < NEXP; e++) {
#pragma unroll
        for (int off = 16; off > 0; off >>= 1)
            acc[e] += __shfl_xor_sync(0xffffffffu, acc[e], off);
    }
    if (lane == 0) {
        float mx = acc[0];
#pragma unroll
        for (int e = 1; e < NEXP; e++) mx = fmaxf(mx, acc[e]);
        float s = 0.f;
#pragma unroll
        for (int e = 0; e < NEXP; e++) { acc[e] = expf(acc[e] - mx); s += acc[e]; }
        float inv = 1.f / s;
#pragma unroll
        for (int e = 0; e < NEXP; e++) gate[warp * NEXP + e] = acc[e] * inv;
    }
}

// ---------------------------------------------------------------------------
// Tiled GEMM, C[M,N] = A[M,K] @ B[K,N] (+ bias, + epilogue).
// A row-major stride K (contiguous in k). B row-major stride N (contiguous n).
// 256 threads, BM=BN=128, BK=16, 8x8 microtile, f32x2 packed inner product.
// EPI 0: C = gelu(AB + bias)              (write h)
// EPI 1: out (+)= gate[row,e] * (AB+bias) (gated accumulate)
// ---------------------------------------------------------------------------
template <int EPI>
__global__ void __launch_bounds__(256, 2) moe_gemm(
    const float* __restrict__ A, const float* __restrict__ B,
    const float* __restrict__ bias, const float* __restrict__ gate,
    float* __restrict__ C, int M, int N, int K, int expert, int first)
{
    __shared__ float As[BK][BM + 4];
    __shared__ float Bs[BK][BN + 4];

    const int tid = threadIdx.x;
    const int tx = tid & 15;        // n-dir, 16
    const int ty = tid >> 4;        // m-dir, 16
    const int m0 = blockIdx.y * BM;
    const int n0 = blockIdx.x * BN;

    unsigned long long acc[8][4];
#pragma unroll
    for (int m = 0; m < 8; m++)
#pragma unroll
        for (int np = 0; np < 4; np++) acc[m][np] = 0ull;

    for (int k0 = 0; k0 < K; k0 += BK) {
        // --- load A tile (transposed into As[k][m]) ---
#pragma unroll
        for (int i = 0; i < 2; i++) {
            int f   = tid + i * 256;        // 512 float4 loads
            int row = f >> 2;
            int kq  = (f & 3) * 4;
            float4 v = *reinterpret_cast<const float4*>(
                &A[(size_t)(m0 + row) * K + k0 + kq]);
            As[kq + 0][row] = v.x;
            As[kq + 1][row] = v.y;
            As[kq + 2][row] = v.z;
            As[kq + 3][row] = v.w;
        }
        // --- load B tile (direct) ---
#pragma unroll
        for (int i = 0; i < 2; i++) {
            int f  = tid + i * 256;
            int kr = f >> 5;
            int c  = (f & 31) * 4;
            float4 v = *reinterpret_cast<const float4*>(
                &B[(size_t)(k0 + kr) * N + n0 + c]);
            *reinterpret_cast<float4*>(&Bs[kr][c]) = v;
        }
        __syncthreads();

#pragma unroll
        for (int k = 0; k < BK; k++) {
            // B pairs are adjacent floats in smem == native f32x2 layout.
            const unsigned long long* brow =
                reinterpret_cast<const unsigned long long*>(&Bs[k][tx * 8]);
            unsigned long long bp0 = brow[0], bp1 = brow[1],
                               bp2 = brow[2], bp3 = brow[3];
            float4 a0 = *reinterpret_cast<const float4*>(&As[k][ty * 8]);
            float4 a1 = *reinterpret_cast<const float4*>(&As[k][ty * 8 + 4]);
            float av[8] = {a0.x, a0.y, a0.z, a0.w, a1.x, a1.y, a1.z, a1.w};
#pragma unroll
            for (int m = 0; m < 8; m++) {
                unsigned long long a2 = pack2(av[m], av[m]);
                fma2(acc[m][0], a2, bp0);
                fma2(acc[m][1], a2, bp1);
                fma2(acc[m][2], a2, bp2);
                fma2(acc[m][3], a2, bp3);
            }
        }
        __syncthreads();
    }

    // --- epilogue ---
    const int row_base = m0 + ty * 8;
    const int col_base = n0 + tx * 8;
#pragma unroll
    for (int m = 0; m < 8; m++) {
        int r = row_base + m;
        float gv = 0.f;
        if (EPI == 1) gv = gate[r * NEXP + expert];
        float* crow = &C[(size_t)r * N + col_base];
#pragma unroll
        for (int np = 0; np < 4; np++) {
            float2 v = unpack2(acc[m][np]);
            int c = np * 2;
            v.x += bias[col_base + c];
            v.y += bias[col_base + c + 1];
            if (EPI == 0) {
                v.x = gelu_exact(v.x);
                v.y = gelu_exact(v.y);
                *reinterpret_cast<float2*>(&crow[c]) = v;
            } else {
                v.x *= gv;
                v.y *= gv;
                if (first) {
                    *reinterpret_cast<float2*>(&crow[c]) = v;
                } else {
                    float2 o = *reinterpret_cast<float2*>(&crow[c]);
                    o.x += v.x; o.y += v.y;
                    *reinterpret_cast<float2*>(&crow[c]) = o;
                }
            }
        }
    }
}

// ---------------------------------------------------------------------------
extern "C" void kernel_launch(void* const* d_in, const int* in_sizes, int n_in,
                              void* d_out, int out_size) {
    const float* x  = (const float*)d_in[0];
    const float* Wg = (const float*)d_in[1];
    const float* W1 = (const float*)d_in[2];
    const float* b1 = (const float*)d_in[3];
    const float* W2 = (const float*)d_in[4];
    const float* b2 = (const float*)d_in[5];
    float* out = (float*)d_out;

    float* hbuf = nullptr;
    float* gbuf = nullptr;
    cudaGetSymbolAddress((void**)&hbuf, g_h);
    cudaGetSymbolAddress((void**)&gbuf, g_gate);

    // Gate softmax: 8 warps/block, 512 blocks.
    gate_kernel<<<T_TOK / 8, 256>>>(x, Wg, gbuf);

    dim3 grid1(INTER / BN, T_TOK / BM);  // GEMM1: M=T, N=I, K=H
    dim3 grid2(HID / BN, T_TOK / BM);    // GEMM2: M=T, N=H, K=I

    for (int e = 0; e < NEXP; e++) {
        const float* W1e = W1 + (size_t)e * HID * INTER;
        const float* b1e = b1 + (size_t)e * INTER;
        const float* W2e = W2 + (size_t)e * INTER * HID;
        const float* b2e = b2 + (size_t)e * HID;

        moe_gemm<0><<<grid1, 256>>>(x, W1e, b1e, nullptr, hbuf,
                                    T_TOK, INTER, HID, e, 0);
        moe_gemm<1><<<grid2, 256>>>(hbuf, W2e, b2e, gbuf, out,
                                    T_TOK, HID, INTER, e, e == 0);
    }
}

// round 5
// speedup vs baseline: 2.1609x; 2.1609x over previous
#include <cuda_runtime.h>
#include <cuda_bf16.h>
#include <cstdint>

#define T_TOK 4096
#define HID   1024
#define INTER 4096
#define NEXP  8

typedef unsigned short u16;
typedef unsigned int   u32;
typedef unsigned long long u64;

// ---------------------------------------------------------------------------
// Device scratch (bf16 hi/lo split operands, gate scores)
// ---------------------------------------------------------------------------
__device__ u16 g_xhi[(size_t)T_TOK * HID];
__device__ u16 g_xlo[(size_t)T_TOK * HID];
__device__ u16 g_w1hi[(size_t)NEXP * HID * INTER];   // [E][I][H] transposed
__device__ u16 g_w1lo[(size_t)NEXP * HID * INTER];
__device__ u16 g_w2hi[(size_t)NEXP * HID * INTER];   // [E][H][I] transposed
__device__ u16 g_w2lo[(size_t)NEXP * HID * INTER];
__device__ u16 g_hhi[(size_t)T_TOK * INTER];
__device__ u16 g_hlo[(size_t)T_TOK * INTER];
__device__ float g_gate[T_TOK * NEXP];

// ---------------------------------------------------------------------------
// Helpers
// ---------------------------------------------------------------------------
__device__ __forceinline__ u32 smem_u32(const void* p) {
    u32 a;
    asm("{ .reg .u64 t; cvta.to.shared.u64 t, %1; cvt.u32.u64 %0, t; }"
        : "=r"(a) : "l"(p));
    return a;
}
__device__ __forceinline__ void cp16(u32 dst, const void* src) {
    asm volatile("cp.async.cg.shared.global [%0], [%1], 16;"
                 :: "r"(dst), "l"(src));
}
__device__ __forceinline__ void ldm_x4(u32& r0, u32& r1, u32& r2, u32& r3, u32 a) {
    asm volatile("ldmatrix.sync.aligned.m8n8.x4.shared.b16 {%0,%1,%2,%3}, [%4];"
                 : "=r"(r0), "=r"(r1), "=r"(r2), "=r"(r3) : "r"(a));
}
__device__ __forceinline__ void mma_bf16(float* c, const u32* a, const u32* b) {
    asm volatile("mma.sync.aligned.m16n8k16.row.col.f32.bf16.bf16.f32 "
                 "{%0,%1,%2,%3}, {%4,%5,%6,%7}, {%8,%9}, {%0,%1,%2,%3};"
                 : "+f"(c[0]), "+f"(c[1]), "+f"(c[2]), "+f"(c[3])
                 : "r"(a[0]), "r"(a[1]), "r"(a[2]), "r"(a[3]),
                   "r"(b[0]), "r"(b[1]));
}
__device__ __forceinline__ void split2(float v, u16& h, u16& l) {
    __nv_bfloat16 bh = __float2bfloat16(v);
    h = __bfloat16_as_ushort(bh);
    l = __bfloat16_as_ushort(__float2bfloat16(v - __bfloat162float(bh)));
}
__device__ __forceinline__ float gelu_exact(float v) { return v * normcdff(v); }

// ---------------------------------------------------------------------------
// Gate: logits = x @ Wg^T, softmax over E=8. One warp per token.
// ---------------------------------------------------------------------------
__global__ void gate_kernel(const float* __restrict__ x,
                            const float* __restrict__ Wg,
                            float* __restrict__ gate) {
    int warp = (blockIdx.x * blockDim.x + threadIdx.x) >> 5;
    int lane = threadIdx.x & 31;
    if (warp >= T_TOK) return;
    const float* xr = x + (size_t)warp * HID;
    float acc[NEXP];
#pragma unroll
    for (int e = 0; e < NEXP; e++) acc[e] = 0.f;
    for (int k = lane; k < HID; k += 32) {
        float xv = xr[k];
#pragma unroll
        for (int e = 0; e < NEXP; e++) acc[e] = fmaf(xv, Wg[e * HID + k], acc[e]);
    }
#pragma unroll
    for (int e = 0; e < NEXP; e++)
#pragma unroll
        for (int off = 16; off > 0; off >>= 1)
            acc[e] += __shfl_xor_sync(0xffffffffu, acc[e], off);
    if (lane == 0) {
        float mx = acc[0];
#pragma unroll
        for (int e = 1; e < NEXP; e++) mx = fmaxf(mx, acc[e]);
        float s = 0.f;
#pragma unroll
        for (int e = 0; e < NEXP; e++) { acc[e] = expf(acc[e] - mx); s += acc[e]; }
        float inv = 1.f / s;
#pragma unroll
        for (int e = 0; e < NEXP; e++) gate[warp * NEXP + e] = acc[e] * inv;
    }
}

// ---------------------------------------------------------------------------
// x -> bf16 hi/lo split (vectorized, row-major preserved)
// ---------------------------------------------------------------------------
__global__ void split_kernel(const float* __restrict__ in, u16* __restrict__ hi,
                             u16* __restrict__ lo, size_t n4) {
    size_t i = (size_t)blockIdx.x * blockDim.x + threadIdx.x;
    if (i >= n4) return;
    float4 v = reinterpret_cast<const float4*>(in)[i];
    u16 h[4], l[4];
    split2(v.x, h[0], l[0]); split2(v.y, h[1], l[1]);
    split2(v.z, h[2], l[2]); split2(v.w, h[3], l[3]);
    reinterpret_cast<u64*>(hi)[i] = *reinterpret_cast<u64*>(h);
    reinterpret_cast<u64*>(lo)[i] = *reinterpret_cast<u64*>(l);
}

// ---------------------------------------------------------------------------
// W [E][R][C] fp32 -> transposed bf16 hi/lo [E][C][R]
// ---------------------------------------------------------------------------
__global__ void tsplit_kernel(const float* __restrict__ W, u16* __restrict__ thi,
                              u16* __restrict__ tlo, int R, int C) {
    __shared__ float t[32][33];
    int e = blockIdx.z;
    const float* Win = W + (size_t)e * R * C;
    u16* oh = thi + (size_t)e * R * C;
    u16* ol = tlo + (size_t)e * R * C;
    int c0 = blockIdx.x * 32, r0 = blockIdx.y * 32;
    int tx = threadIdx.x, ty = threadIdx.y;  // (32, 8)
#pragma unroll
    for (int i = 0; i < 32; i += 8)
        t[ty + i][tx] = Win[(size_t)(r0 + ty + i) * C + c0 + tx];
    __syncthreads();
#pragma unroll
    for (int i = 0; i < 32; i += 8) {
        float v = t[tx][ty + i];
        size_t o = (size_t)(c0 + ty + i) * R + r0 + tx;
        u16 h, l; split2(v, h, l);
        oh[o] = h; ol[o] = l;
    }
}

// ---------------------------------------------------------------------------
// mma.sync GEMM: C[M,N] = (Ahi+Alo)[M,K] @ (Bhi+Blo)[N,K]^T  (3-term bf16)
// 128x128 CTA tile, BK=32, 512 threads (16 warps, 32x32 warp tiles),
// cp.async double buffer, 80B-padded SMEM rows (conflict-free ldmatrix).
// EPI 0: h_{hi,lo} = split(gelu(AB + bias))
// EPI 1: out (+)= gate[r,e] * (AB + bias)
// ---------------------------------------------------------------------------
#define ROWB   80                        // padded row stride in bytes (32 bf16 + 8 pad)
#define TILEB  (128 * ROWB)              // 10240 B per operand tile
#define BUFB   (4 * TILEB)               // 40960 B per stage buffer
#define SM_BYTES (2 * BUFB)              // 81920 B

template <int EPI>
__global__ void __launch_bounds__(512, 1) mma_gemm(
    const u16* __restrict__ Ahi, const u16* __restrict__ Alo,
    const u16* __restrict__ Bhi, const u16* __restrict__ Blo,
    const float* __restrict__ bias, const float* __restrict__ gate,
    float* __restrict__ Cf, u16* __restrict__ Chi, u16* __restrict__ Clo,
    int K, int OPITCH, int expert, int first)
{
    extern __shared__ char sm[];
    const u32 sb = smem_u32(sm);

    const int tid  = threadIdx.x;
    const int wid  = tid >> 5;
    const int lane = tid & 31;
    const int wm   = wid & 3;       // 4 warps in M, 32 rows each
    const int wn   = wid >> 2;      // 4 warps in N, 32 cols each
    const int m0   = blockIdx.y * 128;
    const int n0   = blockIdx.x * 128;

    const u16* gsrc[4] = { Ahi + (size_t)m0 * K, Alo + (size_t)m0 * K,
                           Bhi + (size_t)n0 * K, Blo + (size_t)n0 * K };

    const int lrow = tid >> 2;       // 128 rows
    const int lch  = tid & 3;        // 4 x 16B chunks per row

    // ldmatrix lane addressing (byte offsets within a tile)
    const u32 a_off = (u32)(lane & 15) * ROWB + (u32)(lane >> 4) * 16;
    const u32 b_off = ((u32)(lane & 7) + (u32)((lane >> 4) & 1) * 8) * ROWB
                    + (u32)((lane >> 3) & 1) * 16;

    float acc[2][4][4];
#pragma unroll
    for (int i = 0; i < 2; i++)
#pragma unroll
        for (int j = 0; j < 4; j++)
#pragma unroll
            for (int q = 0; q < 4; q++) acc[i][j][q] = 0.f;

    const int nst = K / 32;

    // ---- stage loader ----
    auto load_stage = [&](int buf, int k0) {
        u32 dbase = sb + (u32)buf * BUFB + (u32)lrow * ROWB + (u32)lch * 16;
#pragma unroll
        for (int t = 0; t < 4; t++)
            cp16(dbase + (u32)t * TILEB,
                 gsrc[t] + (size_t)lrow * K + k0 + lch * 8);
        asm volatile("cp.async.commit_group;" ::: "memory");
    };

    load_stage(0, 0);

    for (int s = 0; s < nst; s++) {
        if (s + 1 < nst) {
            load_stage((s + 1) & 1, (s + 1) * 32);
            asm volatile("cp.async.wait_group 1;" ::: "memory");
        } else {
            asm volatile("cp.async.wait_group 0;" ::: "memory");
        }
        __syncthreads();

        const u32 base = sb + (u32)(s & 1) * BUFB;
        const u32 aW = base + (u32)(wm * 32) * ROWB;           // A rows for this warp
        const u32 bW = base + 2 * TILEB + (u32)(wn * 32) * ROWB;

#pragma unroll
        for (int ks = 0; ks < 2; ks++) {
            const u32 kb = (u32)ks * 32;                        // 16 bf16 = 32B
            u32 ah[2][4], al[2][4], bh[4][2], bl[4][2];
#pragma unroll
            for (int mf = 0; mf < 2; mf++) {
                u32 ad = aW + (u32)(mf * 16) * ROWB + a_off + kb;
                ldm_x4(ah[mf][0], ah[mf][1], ah[mf][2], ah[mf][3], ad);
                ldm_x4(al[mf][0], al[mf][1], al[mf][2], al[mf][3], ad + TILEB);
            }
#pragma unroll
            for (int half = 0; half < 2; half++) {
                u32 bd = bW + (u32)(half * 16) * ROWB + b_off + kb;
                ldm_x4(bh[half * 2][0], bh[half * 2][1],
                       bh[half * 2 + 1][0], bh[half * 2 + 1][1], bd);
                ldm_x4(bl[half * 2][0], bl[half * 2][1],
                       bl[half * 2 + 1][0], bl[half * 2 + 1][1], bd + TILEB);
            }
#pragma unroll
            for (int mf = 0; mf < 2; mf++)
#pragma unroll
                for (int nf = 0; nf < 4; nf++) {
                    mma_bf16(acc[mf][nf], ah[mf], bh[nf]);
                    mma_bf16(acc[mf][nf], ah[mf], bl[nf]);
                    mma_bf16(acc[mf][nf], al[mf], bh[nf]);
                }
        }
        __syncthreads();
    }

    // ---- epilogue ----
    const int g  = lane >> 2;           // row within fragment
    const int tg = lane & 3;            // col pair index
#pragma unroll
    for (int mf = 0; mf < 2; mf++) {
#pragma unroll
        for (int half = 0; half < 2; half++) {   // c0/c1 vs c2/c3 (row, row+8)
            int r = m0 + wm * 32 + mf * 16 + g + half * 8;
            float gv = 0.f;
            if (EPI == 1) gv = gate[r * NEXP + expert];
#pragma unroll
            for (int nf = 0; nf < 4; nf++) {
                int c = n0 + wn * 32 + nf * 8 + tg * 2;
                float v0 = acc[mf][nf][half * 2 + 0] + bias[c];
                float v1 = acc[mf][nf][half * 2 + 1] + bias[c + 1];
                if (EPI == 0) {
                    u16 h0, l0, h1, l1;
                    split2(gelu_exact(v0), h0, l0);
                    split2(gelu_exact(v1), h1, l1);
                    *reinterpret_cast<u32*>(Chi + (size_t)r * OPITCH + c) =
                        (u32)h0 | ((u32)h1 << 16);
                    *reinterpret_cast<u32*>(Clo + (size_t)r * OPITCH + c) =
                        (u32)l0 | ((u32)l1 << 16);
                } else {
                    float2 v = make_float2(v0 * gv, v1 * gv);
                    float2* p = reinterpret_cast<float2*>(Cf + (size_t)r * OPITCH + c);
                    if (!first) { float2 o = *p; v.x += o.x; v.y += o.y; }
                    *p = v;
                }
            }
        }
    }
}

// ---------------------------------------------------------------------------
extern "C" void kernel_launch(void* const* d_in, const int* in_sizes, int n_in,
                              void* d_out, int out_size) {
    const float* x  = (const float*)d_in[0];
    const float* Wg = (const float*)d_in[1];
    const float* W1 = (const float*)d_in[2];
    const float* b1 = (const float*)d_in[3];
    const float* W2 = (const float*)d_in[4];
    const float* b2 = (const float*)d_in[5];
    float* out = (float*)d_out;

    u16 *xhi, *xlo, *w1hi, *w1lo, *w2hi, *w2lo, *hhi, *hlo;
    float* gbuf;
    cudaGetSymbolAddress((void**)&xhi, g_xhi);
    cudaGetSymbolAddress((void**)&xlo, g_xlo);
    cudaGetSymbolAddress((void**)&w1hi, g_w1hi);
    cudaGetSymbolAddress((void**)&w1lo, g_w1lo);
    cudaGetSymbolAddress((void**)&w2hi, g_w2hi);
    cudaGetSymbolAddress((void**)&w2lo, g_w2lo);
    cudaGetSymbolAddress((void**)&hhi, g_hhi);
    cudaGetSymbolAddress((void**)&hlo, g_hlo);
    cudaGetSymbolAddress((void**)&gbuf, g_gate);

    static int attr_done = 0;
    cudaFuncSetAttribute(mma_gemm<0>, cudaFuncAttributeMaxDynamicSharedMemorySize, SM_BYTES);
    cudaFuncSetAttribute(mma_gemm<1>, cudaFuncAttributeMaxDynamicSharedMemorySize, SM_BYTES);
    (void)attr_done;

    gate_kernel<<<T_TOK / 8, 256>>>(x, Wg, gbuf);

    size_t n4x = (size_t)T_TOK * HID / 4;
    split_kernel<<<(unsigned)((n4x + 255) / 256), 256>>>(x, xhi, xlo, n4x);
    tsplit_kernel<<<dim3(INTER / 32, HID / 32, NEXP), dim3(32, 8)>>>(W1, w1hi, w1lo, HID, INTER);
    tsplit_kernel<<<dim3(HID / 32, INTER / 32, NEXP), dim3(32, 8)>>>(W2, w2hi, w2lo, INTER, HID);

    dim3 grid1(INTER / 128, T_TOK / 128);   // 32 x 32
    dim3 grid2(HID / 128, T_TOK / 128);     // 8 x 32

    for (int e = 0; e < NEXP; e++) {
        const size_t wo = (size_t)e * HID * INTER;
        mma_gemm<0><<<grid1, 512, SM_BYTES>>>(
            xhi, xlo, w1hi + wo, w1lo + wo, b1 + (size_t)e * INTER, nullptr,
            nullptr, hhi, hlo, HID, INTER, e, 0);
        mma_gemm<1><<<grid2, 512, SM_BYTES>>>(
            hhi, hlo, w2hi + wo, w2lo + wo, b2 + (size_t)e * HID, gbuf,
            out, nullptr, nullptr, INTER, HID, e, e == 0);
    }
}

// round 6
// speedup vs baseline: 2.4821x; 1.1486x over previous
#include <cuda_runtime.h>
#include <cuda_bf16.h>
#include <cstdint>

#define T_TOK 4096
#define HID   1024
#define INTER 4096
#define NEXP  8

typedef unsigned short u16;
typedef unsigned int   u32;
typedef unsigned long long u64;

// ---------------------------------------------------------------------------
// Device scratch (bf16 hi/lo split operands, gate scores)
// ---------------------------------------------------------------------------
__device__ u16 g_xhi[(size_t)T_TOK * HID];
__device__ u16 g_xlo[(size_t)T_TOK * HID];
__device__ u16 g_w1hi[(size_t)NEXP * HID * INTER];   // [E][I][H] transposed
__device__ u16 g_w1lo[(size_t)NEXP * HID * INTER];
__device__ u16 g_w2hi[(size_t)NEXP * HID * INTER];   // [E][H][I] transposed
__device__ u16 g_w2lo[(size_t)NEXP * HID * INTER];
__device__ u16 g_hhi[(size_t)T_TOK * INTER];
__device__ u16 g_hlo[(size_t)T_TOK * INTER];
__device__ float g_gate[T_TOK * NEXP];

// ---------------------------------------------------------------------------
// Helpers
// ---------------------------------------------------------------------------
__device__ __forceinline__ u32 smem_u32(const void* p) {
    u32 a;
    asm("{ .reg .u64 t; cvta.to.shared.u64 t, %1; cvt.u32.u64 %0, t; }"
        : "=r"(a) : "l"(p));
    return a;
}
__device__ __forceinline__ void cp16(u32 dst, const void* src) {
    asm volatile("cp.async.cg.shared.global [%0], [%1], 16;"
                 :: "r"(dst), "l"(src));
}
__device__ __forceinline__ void ldm_x4(u32& r0, u32& r1, u32& r2, u32& r3, u32 a) {
    asm volatile("ldmatrix.sync.aligned.m8n8.x4.shared.b16 {%0,%1,%2,%3}, [%4];"
                 : "=r"(r0), "=r"(r1), "=r"(r2), "=r"(r3) : "r"(a));
}
__device__ __forceinline__ void mma_bf16(float* c, const u32* a, const u32* b) {
    asm volatile("mma.sync.aligned.m16n8k16.row.col.f32.bf16.bf16.f32 "
                 "{%0,%1,%2,%3}, {%4,%5,%6,%7}, {%8,%9}, {%0,%1,%2,%3};"
                 : "+f"(c[0]), "+f"(c[1]), "+f"(c[2]), "+f"(c[3])
                 : "r"(a[0]), "r"(a[1]), "r"(a[2]), "r"(a[3]),
                   "r"(b[0]), "r"(b[1]));
}
__device__ __forceinline__ void split2(float v, u16& h, u16& l) {
    __nv_bfloat16 bh = __float2bfloat16(v);
    h = __bfloat16_as_ushort(bh);
    l = __bfloat16_as_ushort(__float2bfloat16(v - __bfloat162float(bh)));
}
__device__ __forceinline__ float gelu_exact(float v) { return v * normcdff(v); }

// ---------------------------------------------------------------------------
// Gate: logits = x @ Wg^T, softmax over E=8. One warp per token.
// ---------------------------------------------------------------------------
__global__ void gate_kernel(const float* __restrict__ x,
                            const float* __restrict__ Wg,
                            float* __restrict__ gate) {
    int warp = (blockIdx.x * blockDim.x + threadIdx.x) >> 5;
    int lane = threadIdx.x & 31;
    if (warp >= T_TOK) return;
    const float* xr = x + (size_t)warp * HID;
    float acc[NEXP];
#pragma unroll
    for (int e = 0; e < NEXP; e++) acc[e] = 0.f;
    for (int k = lane; k < HID; k += 32) {
        float xv = xr[k];
#pragma unroll
        for (int e = 0; e < NEXP; e++) acc[e] = fmaf(xv, Wg[e * HID + k], acc[e]);
    }
#pragma unroll
    for (int e = 0; e < NEXP; e++)
#pragma unroll
        for (int off = 16; off > 0; off >>= 1)
            acc[e] += __shfl_xor_sync(0xffffffffu, acc[e], off);
    if (lane == 0) {
        float mx = acc[0];
#pragma unroll
        for (int e = 1; e < NEXP; e++) mx = fmaxf(mx, acc[e]);
        float s = 0.f;
#pragma unroll
        for (int e = 0; e < NEXP; e++) { acc[e] = expf(acc[e] - mx); s += acc[e]; }
        float inv = 1.f / s;
#pragma unroll
        for (int e = 0; e < NEXP; e++) gate[warp * NEXP + e] = acc[e] * inv;
    }
}

// ---------------------------------------------------------------------------
// x -> bf16 hi/lo split (vectorized, row-major preserved)
// ---------------------------------------------------------------------------
__global__ void split_kernel(const float* __restrict__ in, u16* __restrict__ hi,
                             u16* __restrict__ lo, size_t n4) {
    size_t i = (size_t)blockIdx.x * blockDim.x + threadIdx.x;
    if (i >= n4) return;
    float4 v = reinterpret_cast<const float4*>(in)[i];
    u16 h[4], l[4];
    split2(v.x, h[0], l[0]); split2(v.y, h[1], l[1]);
    split2(v.z, h[2], l[2]); split2(v.w, h[3], l[3]);
    reinterpret_cast<u64*>(hi)[i] = *reinterpret_cast<u64*>(h);
    reinterpret_cast<u64*>(lo)[i] = *reinterpret_cast<u64*>(l);
}

// ---------------------------------------------------------------------------
// W [E][R][C] fp32 -> transposed bf16 hi/lo [E][C][R]
// ---------------------------------------------------------------------------
__global__ void tsplit_kernel(const float* __restrict__ W, u16* __restrict__ thi,
                              u16* __restrict__ tlo, int R, int C) {
    __shared__ float t[32][33];
    int e = blockIdx.z;
    const float* Win = W + (size_t)e * R * C;
    u16* oh = thi + (size_t)e * R * C;
    u16* ol = tlo + (size_t)e * R * C;
    int c0 = blockIdx.x * 32, r0 = blockIdx.y * 32;
    int tx = threadIdx.x, ty = threadIdx.y;  // (32, 8)
#pragma unroll
    for (int i = 0; i < 32; i += 8)
        t[ty + i][tx] = Win[(size_t)(r0 + ty + i) * C + c0 + tx];
    __syncthreads();
#pragma unroll
    for (int i = 0; i < 32; i += 8) {
        float v = t[tx][ty + i];
        size_t o = (size_t)(c0 + ty + i) * R + r0 + tx;
        u16 h, l; split2(v, h, l);
        oh[o] = h; ol[o] = l;
    }
}

// ---------------------------------------------------------------------------
// mma.sync GEMM: C[M,N] = (Ahi+Alo)[M,K] @ (Bhi+Blo)[N,K]^T  (3-term bf16)
// 128x128 CTA tile, BK=32, 256 threads (8 warps, 64x32 warp tiles, 2x4 grid),
// cp.async double buffer, 80B-padded rows, 2 CTAs/SM for latency overlap.
// EPI 0: h_{hi,lo} = split(gelu(AB + bias))
// EPI 1: out (+)= gate[r,e] * (AB + bias)
// ---------------------------------------------------------------------------
#define ROWB   80                        // padded row stride (32 bf16 + 16B pad)
#define TILEB  (128 * ROWB)              // 10240 B per operand tile
#define BUFB   (4 * TILEB)               // 40960 B per stage buffer
#define SM_BYTES (2 * BUFB)              // 81920 B -> 2 CTAs/SM (163840 <= 228K)

template <int EPI>
__global__ void __launch_bounds__(256, 2) mma_gemm(
    const u16* __restrict__ Ahi, const u16* __restrict__ Alo,
    const u16* __restrict__ Bhi, const u16* __restrict__ Blo,
    const float* __restrict__ bias, const float* __restrict__ gate,
    float* __restrict__ Cf, u16* __restrict__ Chi, u16* __restrict__ Clo,
    int K, int OPITCH, int expert, int first)
{
    extern __shared__ char sm[];
    const u32 sb = smem_u32(sm);

    const int tid  = threadIdx.x;
    const int wid  = tid >> 5;
    const int lane = tid & 31;
    const int wm   = wid & 1;       // 2 warps in M, 64 rows each
    const int wn   = wid >> 1;      // 4 warps in N, 32 cols each
    const int m0   = blockIdx.y * 128;
    const int n0   = blockIdx.x * 128;

    const u16* gsrc[4] = { Ahi + (size_t)m0 * K, Alo + (size_t)m0 * K,
                           Bhi + (size_t)n0 * K, Blo + (size_t)n0 * K };

    // ldmatrix lane addressing (byte offsets within a tile)
    const u32 a_off = (u32)(lane & 15) * ROWB + (u32)(lane >> 4) * 16;
    const u32 b_off = ((u32)(lane & 7) + (u32)((lane >> 4) & 1) * 8) * ROWB
                    + (u32)((lane >> 3) & 1) * 16;

    float acc[4][4][4];
#pragma unroll
    for (int i = 0; i < 4; i++)
#pragma unroll
        for (int j = 0; j < 4; j++)
#pragma unroll
            for (int q = 0; q < 4; q++) acc[i][j][q] = 0.f;

    const int nst = K / 32;

    // ---- stage loader: 4 tiles x 128 rows x 4 chunks = 2048 cp16 / 256 thr ----
    auto load_stage = [&](int buf, int k0) {
        u32 dbase = sb + (u32)buf * BUFB;
#pragma unroll
        for (int t = 0; t < 4; t++) {
#pragma unroll
            for (int i = 0; i < 2; i++) {
                int idx = tid + i * 256;
                int row = idx >> 2, ch = idx & 3;
                cp16(dbase + (u32)t * TILEB + (u32)row * ROWB + (u32)ch * 16,
                     gsrc[t] + (size_t)row * K + k0 + ch * 8);
            }
        }
        asm volatile("cp.async.commit_group;" ::: "memory");
    };

    load_stage(0, 0);

    for (int s = 0; s < nst; s++) {
        if (s + 1 < nst) {
            load_stage((s + 1) & 1, (s + 1) * 32);
            asm volatile("cp.async.wait_group 1;" ::: "memory");
        } else {
            asm volatile("cp.async.wait_group 0;" ::: "memory");
        }
        __syncthreads();

        const u32 base = sb + (u32)(s & 1) * BUFB;
        const u32 aW = base + (u32)(wm * 64) * ROWB;            // A rows, this warp
        const u32 bW = base + 2 * TILEB + (u32)(wn * 32) * ROWB;

#pragma unroll
        for (int ks = 0; ks < 2; ks++) {
            const u32 kb = (u32)ks * 32;                         // 16 bf16 = 32B
            u32 ah[4][4], al[4][4];
#pragma unroll
            for (int mf = 0; mf < 4; mf++) {
                u32 ad = aW + (u32)(mf * 16) * ROWB + a_off + kb;
                ldm_x4(ah[mf][0], ah[mf][1], ah[mf][2], ah[mf][3], ad);
                ldm_x4(al[mf][0], al[mf][1], al[mf][2], al[mf][3], ad + TILEB);
            }
#pragma unroll
            for (int np = 0; np < 2; np++) {                     // nf pairs
                u32 bh0[2], bh1[2], bl0[2], bl1[2];
                u32 bd = bW + (u32)(np * 16) * ROWB + b_off + kb;
                ldm_x4(bh0[0], bh0[1], bh1[0], bh1[1], bd);
                ldm_x4(bl0[0], bl0[1], bl1[0], bl1[1], bd + TILEB);
#pragma unroll
                for (int mf = 0; mf < 4; mf++) {
                    mma_bf16(acc[mf][np * 2 + 0], ah[mf], bh0);
                    mma_bf16(acc[mf][np * 2 + 0], ah[mf], bl0);
                    mma_bf16(acc[mf][np * 2 + 0], al[mf], bh0);
                    mma_bf16(acc[mf][np * 2 + 1], ah[mf], bh1);
                    mma_bf16(acc[mf][np * 2 + 1], ah[mf], bl1);
                    mma_bf16(acc[mf][np * 2 + 1], al[mf], bh1);
                }
            }
        }
        __syncthreads();
    }

    // ---- epilogue ----
    const int g  = lane >> 2;           // row within fragment
    const int tg = lane & 3;            // col pair index
#pragma unroll
    for (int mf = 0; mf < 4; mf++) {
#pragma unroll
        for (int half = 0; half < 2; half++) {   // c0/c1 vs c2/c3 (row, row+8)
            int r = m0 + wm * 64 + mf * 16 + g + half * 8;
            float gv = 0.f;
            if (EPI == 1) gv = gate[r * NEXP + expert];
#pragma unroll
            for (int nf = 0; nf < 4; nf++) {
                int c = n0 + wn * 32 + nf * 8 + tg * 2;
                float v0 = acc[mf][nf][half * 2 + 0] + bias[c];
                float v1 = acc[mf][nf][half * 2 + 1] + bias[c + 1];
                if (EPI == 0) {
                    u16 h0, l0, h1, l1;
                    split2(gelu_exact(v0), h0, l0);
                    split2(gelu_exact(v1), h1, l1);
                    *reinterpret_cast<u32*>(Chi + (size_t)r * OPITCH + c) =
                        (u32)h0 | ((u32)h1 << 16);
                    *reinterpret_cast<u32*>(Clo + (size_t)r * OPITCH + c) =
                        (u32)l0 | ((u32)l1 << 16);
                } else {
                    float2 v = make_float2(v0 * gv, v1 * gv);
                    float2* p = reinterpret_cast<float2*>(Cf + (size_t)r * OPITCH + c);
                    if (!first) { float2 o = *p; v.x += o.x; v.y += o.y; }
                    *p = v;
                }
            }
        }
    }
}

// ---------------------------------------------------------------------------
extern "C" void kernel_launch(void* const* d_in, const int* in_sizes, int n_in,
                              void* d_out, int out_size) {
    const float* x  = (const float*)d_in[0];
    const float* Wg = (const float*)d_in[1];
    const float* W1 = (const float*)d_in[2];
    const float* b1 = (const float*)d_in[3];
    const float* W2 = (const float*)d_in[4];
    const float* b2 = (const float*)d_in[5];
    float* out = (float*)d_out;

    u16 *xhi, *xlo, *w1hi, *w1lo, *w2hi, *w2lo, *hhi, *hlo;
    float* gbuf;
    cudaGetSymbolAddress((void**)&xhi, g_xhi);
    cudaGetSymbolAddress((void**)&xlo, g_xlo);
    cudaGetSymbolAddress((void**)&w1hi, g_w1hi);
    cudaGetSymbolAddress((void**)&w1lo, g_w1lo);
    cudaGetSymbolAddress((void**)&w2hi, g_w2hi);
    cudaGetSymbolAddress((void**)&w2lo, g_w2lo);
    cudaGetSymbolAddress((void**)&hhi, g_hhi);
    cudaGetSymbolAddress((void**)&hlo, g_hlo);
    cudaGetSymbolAddress((void**)&gbuf, g_gate);

    cudaFuncSetAttribute(mma_gemm<0>, cudaFuncAttributeMaxDynamicSharedMemorySize, SM_BYTES);
    cudaFuncSetAttribute(mma_gemm<1>, cudaFuncAttributeMaxDynamicSharedMemorySize, SM_BYTES);

    gate_kernel<<<T_TOK / 8, 256>>>(x, Wg, gbuf);

    size_t n4x = (size_t)T_TOK * HID / 4;
    split_kernel<<<(unsigned)((n4x + 255) / 256), 256>>>(x, xhi, xlo, n4x);
    tsplit_kernel<<<dim3(INTER / 32, HID / 32, NEXP), dim3(32, 8)>>>(W1, w1hi, w1lo, HID, INTER);
    tsplit_kernel<<<dim3(HID / 32, INTER / 32, NEXP), dim3(32, 8)>>>(W2, w2hi, w2lo, INTER, HID);

    dim3 grid1(INTER / 128, T_TOK / 128);   // 32 x 32
    dim3 grid2(HID / 128, T_TOK / 128);     // 8 x 32

    for (int e = 0; e < NEXP; e++) {
        const size_t wo = (size_t)e * HID * INTER;
        mma_gemm<0><<<grid1, 256, SM_BYTES>>>(
            xhi, xlo, w1hi + wo, w1lo + wo, b1 + (size_t)e * INTER, nullptr,
            nullptr, hhi, hlo, HID, INTER, e, 0);
        mma_gemm<1><<<grid2, 256, SM_BYTES>>>(
            hhi, hlo, w2hi + wo, w2lo + wo, b2 + (size_t)e * HID, gbuf,
            out, nullptr, nullptr, INTER, HID, e, e == 0);
    }
}

// round 7
// speedup vs baseline: 3.0467x; 1.2275x over previous
#include <cuda_runtime.h>
#include <cuda_bf16.h>
#include <cstdint>

#define T_TOK 4096
#define HID   1024
#define INTER 4096
#define NEXP  8

typedef unsigned short u16;
typedef unsigned int   u32;
typedef unsigned long long u64;

// ---------------------------------------------------------------------------
// Device scratch
// ---------------------------------------------------------------------------
__device__ u16 g_xhi[(size_t)T_TOK * HID];
__device__ u16 g_xlo[(size_t)T_TOK * HID];
__device__ u16 g_w1hi[(size_t)NEXP * HID * INTER];   // [E][I][H] transposed
__device__ u16 g_w1lo[(size_t)NEXP * HID * INTER];
__device__ u16 g_w2hi[(size_t)NEXP * HID * INTER];   // [E][H][I] transposed
__device__ u16 g_w2lo[(size_t)NEXP * HID * INTER];
__device__ u16 g_hhi[(size_t)NEXP * T_TOK * INTER];  // per-expert h (bf16 hi/lo)
__device__ u16 g_hlo[(size_t)NEXP * T_TOK * INTER];
__device__ float g_y[(size_t)NEXP * T_TOK * HID];    // per-expert y (fp32)
__device__ float g_gate[T_TOK * NEXP];

// ---------------------------------------------------------------------------
// Helpers
// ---------------------------------------------------------------------------
__device__ __forceinline__ u32 smem_u32(const void* p) {
    u32 a;
    asm("{ .reg .u64 t; cvta.to.shared.u64 t, %1; cvt.u32.u64 %0, t; }"
        : "=r"(a) : "l"(p));
    return a;
}
__device__ __forceinline__ void cp16(u32 dst, const void* src) {
    asm volatile("cp.async.cg.shared.global [%0], [%1], 16;"
                 :: "r"(dst), "l"(src));
}
__device__ __forceinline__ void ldm_x4(u32& r0, u32& r1, u32& r2, u32& r3, u32 a) {
    asm volatile("ldmatrix.sync.aligned.m8n8.x4.shared.b16 {%0,%1,%2,%3}, [%4];"
                 : "=r"(r0), "=r"(r1), "=r"(r2), "=r"(r3) : "r"(a));
}
__device__ __forceinline__ void mma_bf16(float* c, const u32* a, const u32* b) {
    asm volatile("mma.sync.aligned.m16n8k16.row.col.f32.bf16.bf16.f32 "
                 "{%0,%1,%2,%3}, {%4,%5,%6,%7}, {%8,%9}, {%0,%1,%2,%3};"
                 : "+f"(c[0]), "+f"(c[1]), "+f"(c[2]), "+f"(c[3])
                 : "r"(a[0]), "r"(a[1]), "r"(a[2]), "r"(a[3]),
                   "r"(b[0]), "r"(b[1]));
}
__device__ __forceinline__ void split2(float v, u16& h, u16& l) {
    __nv_bfloat16 bh = __float2bfloat16(v);
    h = __bfloat16_as_ushort(bh);
    l = __bfloat16_as_ushort(__float2bfloat16(v - __bfloat162float(bh)));
}
__device__ __forceinline__ float gelu_exact(float v) { return v * normcdff(v); }

// ---------------------------------------------------------------------------
// Gate: logits = x @ Wg^T, softmax over E=8. One warp per token.
// ---------------------------------------------------------------------------
__global__ void gate_kernel(const float* __restrict__ x,
                            const float* __restrict__ Wg,
                            float* __restrict__ gate) {
    int warp = (blockIdx.x * blockDim.x + threadIdx.x) >> 5;
    int lane = threadIdx.x & 31;
    if (warp >= T_TOK) return;
    const float* xr = x + (size_t)warp * HID;
    float acc[NEXP];
#pragma unroll
    for (int e = 0; e < NEXP; e++) acc[e] = 0.f;
    for (int k = lane; k < HID; k += 32) {
        float xv = xr[k];
#pragma unroll
        for (int e = 0; e < NEXP; e++) acc[e] = fmaf(xv, Wg[e * HID + k], acc[e]);
    }
#pragma unroll
    for (int e = 0; e < NEXP; e++)
#pragma unroll
        for (int off = 16; off > 0; off >>= 1)
            acc[e] += __shfl_xor_sync(0xffffffffu, acc[e], off);
    if (lane == 0) {
        float mx = acc[0];
#pragma unroll
        for (int e = 1; e < NEXP; e++) mx = fmaxf(mx, acc[e]);
        float s = 0.f;
#pragma unroll
        for (int e = 0; e < NEXP; e++) { acc[e] = expf(acc[e] - mx); s += acc[e]; }
        float inv = 1.f / s;
#pragma unroll
        for (int e = 0; e < NEXP; e++) gate[warp * NEXP + e] = acc[e] * inv;
    }
}

// ---------------------------------------------------------------------------
// x -> bf16 hi/lo split
// ---------------------------------------------------------------------------
__global__ void split_kernel(const float* __restrict__ in, u16* __restrict__ hi,
                             u16* __restrict__ lo, size_t n4) {
    size_t i = (size_t)blockIdx.x * blockDim.x + threadIdx.x;
    if (i >= n4) return;
    float4 v = reinterpret_cast<const float4*>(in)[i];
    u16 h[4], l[4];
    split2(v.x, h[0], l[0]); split2(v.y, h[1], l[1]);
    split2(v.z, h[2], l[2]); split2(v.w, h[3], l[3]);
    reinterpret_cast<u64*>(hi)[i] = *reinterpret_cast<u64*>(h);
    reinterpret_cast<u64*>(lo)[i] = *reinterpret_cast<u64*>(l);
}

// ---------------------------------------------------------------------------
// W [E][R][C] fp32 -> transposed bf16 hi/lo [E][C][R]
// ---------------------------------------------------------------------------
__global__ void tsplit_kernel(const float* __restrict__ W, u16* __restrict__ thi,
                              u16* __restrict__ tlo, int R, int C) {
    __shared__ float t[32][33];
    int e = blockIdx.z;
    const float* Win = W + (size_t)e * R * C;
    u16* oh = thi + (size_t)e * R * C;
    u16* ol = tlo + (size_t)e * R * C;
    int c0 = blockIdx.x * 32, r0 = blockIdx.y * 32;
    int tx = threadIdx.x, ty = threadIdx.y;  // (32, 8)
#pragma unroll
    for (int i = 0; i < 32; i += 8)
        t[ty + i][tx] = Win[(size_t)(r0 + ty + i) * C + c0 + tx];
    __syncthreads();
#pragma unroll
    for (int i = 0; i < 32; i += 8) {
        float v = t[tx][ty + i];
        size_t o = (size_t)(c0 + ty + i) * R + r0 + tx;
        u16 h, l; split2(v, h, l);
        oh[o] = h; ol[o] = l;
    }
}

// ---------------------------------------------------------------------------
// Final reduce: out[t,h] = sum_e gate[t,e] * y[e,t,h]
// ---------------------------------------------------------------------------
__global__ void reduce_kernel(const float* __restrict__ y,
                              const float* __restrict__ gate,
                              float* __restrict__ out) {
    size_t idx = (size_t)blockIdx.x * blockDim.x + threadIdx.x;  // over T*H/4
    if (idx >= (size_t)T_TOK * HID / 4) return;
    int t = (int)(idx / (HID / 4));
    float4 s = make_float4(0.f, 0.f, 0.f, 0.f);
#pragma unroll
    for (int e = 0; e < NEXP; e++) {
        float g = gate[t * NEXP + e];
        float4 v = reinterpret_cast<const float4*>(y + (size_t)e * T_TOK * HID)[idx];
        s.x = fmaf(g, v.x, s.x); s.y = fmaf(g, v.y, s.y);
        s.z = fmaf(g, v.z, s.z); s.w = fmaf(g, v.w, s.w);
    }
    reinterpret_cast<float4*>(out)[idx] = s;
}

// ---------------------------------------------------------------------------
// mma.sync GEMM over grid.z experts: C = (Ahi+Alo) @ (Bhi+Blo)^T (3-term bf16)
// 128x128 CTA tile, BK=32, 256 threads (8 warps, 64x32 warp tiles),
// SW128-XOR packed hi|lo rows (128B), 3-stage cp.async ring, 1 sync/stage,
// 2 CTAs/SM. EPI 0: h=split(gelu(.+b)); EPI 1: y = . + b (fp32)
// ---------------------------------------------------------------------------
#define STAGEB 32768                     // A(16K) + B(16K) per stage
#define NSTAGE 3
#define SM_BYTES (NSTAGE * STAGEB)       // 98304 -> 2 CTAs/SM

__device__ __forceinline__ u32 swz(u32 row, u32 ch) {   // byte offset in 128B-row tile
    return row * 128 + ((ch ^ (row & 7)) << 4);
}

template <int EPI>
__global__ void __launch_bounds__(256, 2) mma_gemm(
    const u16* __restrict__ Ahi, const u16* __restrict__ Alo, size_t aStride,
    const u16* __restrict__ Bhi, const u16* __restrict__ Blo,
    const float* __restrict__ bias,
    float* __restrict__ Cf, u16* __restrict__ Chi, u16* __restrict__ Clo,
    size_t cStride, int K)
{
    extern __shared__ char sm[];
    const u32 sb = smem_u32(sm);

    const int tid  = threadIdx.x;
    const int wid  = tid >> 5;
    const int lane = tid & 31;
    const int wm   = wid & 1;       // 2 warps in M, 64 rows each
    const int wn   = wid >> 1;      // 4 warps in N, 32 cols each
    const int m0   = blockIdx.y * 128;
    const int n0   = blockIdx.x * 128;
    const int e    = blockIdx.z;
    const int N    = gridDim.x * 128;

    const size_t wOff = (size_t)e * HID * INTER;
    const u16* srcs[4] = { Ahi + (size_t)e * aStride + (size_t)m0 * K,
                           Alo + (size_t)e * aStride + (size_t)m0 * K,
                           Bhi + wOff + (size_t)n0 * K,
                           Blo + wOff + (size_t)n0 * K };
    bias += (size_t)e * N;

    // ldmatrix lane decomposition
    const u32 a_r  = lane & 15;           // row within 16
    const u32 a_cs = lane >> 4;           // k-chunk select
    const u32 b_r  = (lane & 7) + (((u32)lane >> 4) & 1) * 8;
    const u32 b_cs = ((u32)lane >> 3) & 1;

    float acc[4][4][4];
#pragma unroll
    for (int i = 0; i < 4; i++)
#pragma unroll
        for (int j = 0; j < 4; j++)
#pragma unroll
            for (int q = 0; q < 4; q++) acc[i][j][q] = 0.f;

    const int nst = K / 32;

    // stage loader: 2048 cp16 (A 1024 + B 1024) / 256 threads = 8 each
    auto load_stage = [&](int buf, int k0) {
        u32 dbase = sb + (u32)buf * STAGEB;
#pragma unroll
        for (int i = 0; i < 8; i++) {
            int idx = tid + i * 256;
            int t   = idx >> 10;            // 0 = A tile, 1 = B tile
            int j   = idx & 1023;
            int row = j >> 3, c = j & 7;    // c<4: hi chunks, c>=4: lo chunks
            const u16* s = srcs[t * 2 + (c >> 2)] + (size_t)row * K + k0 + (c & 3) * 8;
            cp16(dbase + (u32)t * 16384 + swz((u32)row, (u32)c), s);
        }
        asm volatile("cp.async.commit_group;" ::: "memory");
    };

    load_stage(0, 0);
    load_stage(1, 32);

    int buf = 0;
    for (int s = 0; s < nst; s++) {
        if (s + 1 < nst) asm volatile("cp.async.wait_group 1;" ::: "memory");
        else             asm volatile("cp.async.wait_group 0;" ::: "memory");
        __syncthreads();
        if (s + 2 < nst) load_stage((s + 2) % NSTAGE ? (s + 2) % NSTAGE : 0, (s + 2) * 32);

        const u32 aT = sb + (u32)buf * STAGEB;
        const u32 bT = aT + 16384;

#pragma unroll
        for (int ks = 0; ks < 2; ks++) {
            const u32 cHi = (u32)ks * 2;          // hi chunks: cHi + cs
            u32 ah[4][4], al[4][4];
#pragma unroll
            for (int mf = 0; mf < 4; mf++) {
                u32 row = (u32)(wm * 64 + mf * 16) + a_r;
                ldm_x4(ah[mf][0], ah[mf][1], ah[mf][2], ah[mf][3],
                       aT + swz(row, cHi + a_cs));
                ldm_x4(al[mf][0], al[mf][1], al[mf][2], al[mf][3],
                       aT + swz(row, cHi + a_cs + 4));
            }
#pragma unroll
            for (int np = 0; np < 2; np++) {
                u32 bh0[2], bh1[2], bl0[2], bl1[2];
                u32 row = (u32)(wn * 32 + np * 16) + b_r;
                ldm_x4(bh0[0], bh0[1], bh1[0], bh1[1], bT + swz(row, cHi + b_cs));
                ldm_x4(bl0[0], bl0[1], bl1[0], bl1[1], bT + swz(row, cHi + b_cs + 4));
#pragma unroll
                for (int mf = 0; mf < 4; mf++) {
                    mma_bf16(acc[mf][np * 2 + 0], ah[mf], bh0);
                    mma_bf16(acc[mf][np * 2 + 0], ah[mf], bl0);
                    mma_bf16(acc[mf][np * 2 + 0], al[mf], bh0);
                    mma_bf16(acc[mf][np * 2 + 1], ah[mf], bh1);
                    mma_bf16(acc[mf][np * 2 + 1], ah[mf], bl1);
                    mma_bf16(acc[mf][np * 2 + 1], al[mf], bh1);
                }
            }
        }
        buf = (buf + 1 == NSTAGE) ? 0 : buf + 1;
    }

    // ---- epilogue ----
    u16* ChiE = Chi;  u16* CloE = Clo;  float* CfE = Cf;
    if (EPI == 0) { ChiE += (size_t)e * cStride; CloE += (size_t)e * cStride; }
    else          { CfE  += (size_t)e * cStride; }

    const int g  = lane >> 2;
    const int tg = lane & 3;
#pragma unroll
    for (int mf = 0; mf < 4; mf++) {
#pragma unroll
        for (int half = 0; half < 2; half++) {
            int r = m0 + wm * 64 + mf * 16 + g + half * 8;
#pragma unroll
            for (int nf = 0; nf < 4; nf++) {
                int c = n0 + wn * 32 + nf * 8 + tg * 2;
                float v0 = acc[mf][nf][half * 2 + 0] + bias[c];
                float v1 = acc[mf][nf][half * 2 + 1] + bias[c + 1];
                if (EPI == 0) {
                    u16 h0, l0, h1, l1;
                    split2(gelu_exact(v0), h0, l0);
                    split2(gelu_exact(v1), h1, l1);
                    *reinterpret_cast<u32*>(ChiE + (size_t)r * N + c) =
                        (u32)h0 | ((u32)h1 << 16);
                    *reinterpret_cast<u32*>(CloE + (size_t)r * N + c) =
                        (u32)l0 | ((u32)l1 << 16);
                } else {
                    *reinterpret_cast<float2*>(CfE + (size_t)r * N + c) =
                        make_float2(v0, v1);
                }
            }
        }
    }
}

// ---------------------------------------------------------------------------
extern "C" void kernel_launch(void* const* d_in, const int* in_sizes, int n_in,
                              void* d_out, int out_size) {
    const float* x  = (const float*)d_in[0];
    const float* Wg = (const float*)d_in[1];
    const float* W1 = (const float*)d_in[2];
    const float* b1 = (const float*)d_in[3];
    const float* W2 = (const float*)d_in[4];
    const float* b2 = (const float*)d_in[5];
    float* out = (float*)d_out;

    u16 *xhi, *xlo, *w1hi, *w1lo, *w2hi, *w2lo, *hhi, *hlo;
    float *gbuf, *ybuf;
    cudaGetSymbolAddress((void**)&xhi, g_xhi);
    cudaGetSymbolAddress((void**)&xlo, g_xlo);
    cudaGetSymbolAddress((void**)&w1hi, g_w1hi);
    cudaGetSymbolAddress((void**)&w1lo, g_w1lo);
    cudaGetSymbolAddress((void**)&w2hi, g_w2hi);
    cudaGetSymbolAddress((void**)&w2lo, g_w2lo);
    cudaGetSymbolAddress((void**)&hhi, g_hhi);
    cudaGetSymbolAddress((void**)&hlo, g_hlo);
    cudaGetSymbolAddress((void**)&gbuf, g_gate);
    cudaGetSymbolAddress((void**)&ybuf, g_y);

    cudaFuncSetAttribute(mma_gemm<0>, cudaFuncAttributeMaxDynamicSharedMemorySize, SM_BYTES);
    cudaFuncSetAttribute(mma_gemm<1>, cudaFuncAttributeMaxDynamicSharedMemorySize, SM_BYTES);

    gate_kernel<<<T_TOK / 8, 256>>>(x, Wg, gbuf);

    size_t n4x = (size_t)T_TOK * HID / 4;
    split_kernel<<<(unsigned)((n4x + 255) / 256), 256>>>(x, xhi, xlo, n4x);
    tsplit_kernel<<<dim3(INTER / 32, HID / 32, NEXP), dim3(32, 8)>>>(W1, w1hi, w1lo, HID, INTER);
    tsplit_kernel<<<dim3(HID / 32, INTER / 32, NEXP), dim3(32, 8)>>>(W2, w2hi, w2lo, INTER, HID);

    // GEMM1 all experts: M=T, N=INTER, K=HID
    mma_gemm<0><<<dim3(INTER / 128, T_TOK / 128, NEXP), 256, SM_BYTES>>>(
        xhi, xlo, 0, w1hi, w1lo, b1,
        nullptr, hhi, hlo, (size_t)T_TOK * INTER, HID);

    // GEMM2 all experts: M=T, N=HID, K=INTER
    mma_gemm<1><<<dim3(HID / 128, T_TOK / 128, NEXP), 256, SM_BYTES>>>(
        hhi, hlo, (size_t)T_TOK * INTER, w2hi, w2lo, b2,
        ybuf, nullptr, nullptr, (size_t)T_TOK * HID, INTER);

    // out = sum_e gate[t,e] * y[e]
    size_t n4o = (size_t)T_TOK * HID / 4;
    reduce_kernel<<<(unsigned)((n4o + 255) / 256), 256>>>(ybuf, gbuf, out);
}

// round 8
// speedup vs baseline: 3.2522x; 1.0674x over previous
#include <cuda_runtime.h>
#include <cuda_bf16.h>
#include <cstdint>

#define T_TOK 4096
#define HID   1024
#define INTER 4096
#define NEXP  8

typedef unsigned short u16;
typedef unsigned int   u32;
typedef unsigned long long u64;

// ---------------------------------------------------------------------------
// Device scratch
// ---------------------------------------------------------------------------
__device__ u16 g_xhi[(size_t)T_TOK * HID];
__device__ u16 g_xlo[(size_t)T_TOK * HID];
__device__ u16 g_w1hi[(size_t)NEXP * HID * INTER];   // [E][I][H] transposed
__device__ u16 g_w1lo[(size_t)NEXP * HID * INTER];
__device__ u16 g_w2hi[(size_t)NEXP * HID * INTER];   // [E][H][I] transposed
__device__ u16 g_w2lo[(size_t)NEXP * HID * INTER];
__device__ u16 g_hhi[(size_t)NEXP * T_TOK * INTER];  // per-expert h (bf16 hi/lo)
__device__ u16 g_hlo[(size_t)NEXP * T_TOK * INTER];
__device__ float g_y[(size_t)NEXP * T_TOK * HID];    // per-expert y (fp32)
__device__ float g_gate[T_TOK * NEXP];

// ---------------------------------------------------------------------------
// Helpers
// ---------------------------------------------------------------------------
__device__ __forceinline__ u32 smem_u32(const void* p) {
    u32 a;
    asm("{ .reg .u64 t; cvta.to.shared.u64 t, %1; cvt.u32.u64 %0, t; }"
        : "=r"(a) : "l"(p));
    return a;
}
__device__ __forceinline__ void cp16(u32 dst, const void* src) {
    asm volatile("cp.async.cg.shared.global [%0], [%1], 16;"
                 :: "r"(dst), "l"(src));
}
__device__ __forceinline__ void ldm_x4(u32& r0, u32& r1, u32& r2, u32& r3, u32 a) {
    asm volatile("ldmatrix.sync.aligned.m8n8.x4.shared.b16 {%0,%1,%2,%3}, [%4];"
                 : "=r"(r0), "=r"(r1), "=r"(r2), "=r"(r3) : "r"(a));
}
__device__ __forceinline__ void mma_bf16(float* c, const u32* a, const u32* b) {
    asm volatile("mma.sync.aligned.m16n8k16.row.col.f32.bf16.bf16.f32 "
                 "{%0,%1,%2,%3}, {%4,%5,%6,%7}, {%8,%9}, {%0,%1,%2,%3};"
                 : "+f"(c[0]), "+f"(c[1]), "+f"(c[2]), "+f"(c[3])
                 : "r"(a[0]), "r"(a[1]), "r"(a[2]), "r"(a[3]),
                   "r"(b[0]), "r"(b[1]));
}
__device__ __forceinline__ void split2(float v, u16& h, u16& l) {
    __nv_bfloat16 bh = __float2bfloat16(v);
    h = __bfloat16_as_ushort(bh);
    l = __bfloat16_as_ushort(__float2bfloat16(v - __bfloat162float(bh)));
}
__device__ __forceinline__ float gelu_exact(float v) { return v * normcdff(v); }

// ---------------------------------------------------------------------------
// Gate: logits = x @ Wg^T, softmax over E=8. One warp per token.
// ---------------------------------------------------------------------------
__global__ void gate_kernel(const float* __restrict__ x,
                            const float* __restrict__ Wg,
                            float* __restrict__ gate) {
    int warp = (blockIdx.x * blockDim.x + threadIdx.x) >> 5;
    int lane = threadIdx.x & 31;
    if (warp >= T_TOK) return;
    const float* xr = x + (size_t)warp * HID;
    float acc[NEXP];
#pragma unroll
    for (int e = 0; e < NEXP; e++) acc[e] = 0.f;
    for (int k = lane; k < HID; k += 32) {
        float xv = xr[k];
#pragma unroll
        for (int e = 0; e < NEXP; e++) acc[e] = fmaf(xv, Wg[e * HID + k], acc[e]);
    }
#pragma unroll
    for (int e = 0; e < NEXP; e++)
#pragma unroll
        for (int off = 16; off > 0; off >>= 1)
            acc[e] += __shfl_xor_sync(0xffffffffu, acc[e], off);
    if (lane == 0) {
        float mx = acc[0];
#pragma unroll
        for (int e = 1; e < NEXP; e++) mx = fmaxf(mx, acc[e]);
        float s = 0.f;
#pragma unroll
        for (int e = 0; e < NEXP; e++) { acc[e] = expf(acc[e] - mx); s += acc[e]; }
        float inv = 1.f / s;
#pragma unroll
        for (int e = 0; e < NEXP; e++) gate[warp * NEXP + e] = acc[e] * inv;
    }
}

// ---------------------------------------------------------------------------
// x -> bf16 hi/lo split
// ---------------------------------------------------------------------------
__global__ void split_kernel(const float* __restrict__ in, u16* __restrict__ hi,
                             u16* __restrict__ lo, size_t n4) {
    size_t i = (size_t)blockIdx.x * blockDim.x + threadIdx.x;
    if (i >= n4) return;
    float4 v = reinterpret_cast<const float4*>(in)[i];
    u16 h[4], l[4];
    split2(v.x, h[0], l[0]); split2(v.y, h[1], l[1]);
    split2(v.z, h[2], l[2]); split2(v.w, h[3], l[3]);
    reinterpret_cast<u64*>(hi)[i] = *reinterpret_cast<u64*>(h);
    reinterpret_cast<u64*>(lo)[i] = *reinterpret_cast<u64*>(l);
}

// ---------------------------------------------------------------------------
// W [E][R][C] fp32 -> transposed bf16 hi/lo [E][C][R]
// 64(R) x 32(C) tiles; paired u32 stores along R for full-width writes.
// ---------------------------------------------------------------------------
__global__ void tsplit_kernel(const float* __restrict__ W, u16* __restrict__ thi,
                              u16* __restrict__ tlo, int R, int C) {
    __shared__ float t[64][33];
    int e = blockIdx.z;
    const float* Win = W + (size_t)e * R * C;
    u16* oh = thi + (size_t)e * R * C;
    u16* ol = tlo + (size_t)e * R * C;
    int c0 = blockIdx.x * 32, r0 = blockIdx.y * 64;
    int tx = threadIdx.x, ty = threadIdx.y;  // (32, 8)
#pragma unroll
    for (int i = 0; i < 8; i++)
        t[ty + i * 8][tx] = Win[(size_t)(r0 + ty + i * 8) * C + c0 + tx];
    __syncthreads();
#pragma unroll
    for (int i = 0; i < 4; i++) {
        int crow = ty + i * 8;
        float v0 = t[2 * tx + 0][crow];
        float v1 = t[2 * tx + 1][crow];
        u16 h0, l0, h1, l1;
        split2(v0, h0, l0);
        split2(v1, h1, l1);
        size_t o = (size_t)(c0 + crow) * R + r0 + 2 * tx;
        *reinterpret_cast<u32*>(oh + o) = (u32)h0 | ((u32)h1 << 16);
        *reinterpret_cast<u32*>(ol + o) = (u32)l0 | ((u32)l1 << 16);
    }
}

// ---------------------------------------------------------------------------
// Final reduce: out[t,h] = sum_e gate[t,e] * y[e,t,h]
// ---------------------------------------------------------------------------
__global__ void reduce_kernel(const float* __restrict__ y,
                              const float* __restrict__ gate,
                              float* __restrict__ out) {
    size_t idx = (size_t)blockIdx.x * blockDim.x + threadIdx.x;  // over T*H/4
    if (idx >= (size_t)T_TOK * HID / 4) return;
    int t = (int)(idx / (HID / 4));
    float4 s = make_float4(0.f, 0.f, 0.f, 0.f);
#pragma unroll
    for (int e = 0; e < NEXP; e++) {
        float g = gate[t * NEXP + e];
        float4 v = reinterpret_cast<const float4*>(y + (size_t)e * T_TOK * HID)[idx];
        s.x = fmaf(g, v.x, s.x); s.y = fmaf(g, v.y, s.y);
        s.z = fmaf(g, v.z, s.z); s.w = fmaf(g, v.w, s.w);
    }
    reinterpret_cast<float4*>(out)[idx] = s;
}

// ---------------------------------------------------------------------------
// mma.sync GEMM over grid.z experts: C = (Ahi+Alo) @ (Bhi+Blo)^T (3-term bf16)
// 128x128 CTA tile, BK=32, 128 threads (4 warps, 64x64 warp tiles, 2x2 grid),
// SW128-XOR packed hi|lo rows (128B), 3-stage cp.async ring, 1 sync/stage,
// 2 CTAs/SM. EPI 0: h=split(gelu(.+b)); EPI 1: y = . + b (fp32)
// ---------------------------------------------------------------------------
#define STAGEB 32768                     // A(16K) + B(16K) per stage
#define NSTAGE 3
#define SM_BYTES (NSTAGE * STAGEB)       // 98304 -> 2 CTAs/SM

__device__ __forceinline__ u32 swz(u32 row, u32 ch) {   // byte offset in 128B-row tile
    return row * 128 + ((ch ^ (row & 7)) << 4);
}

template <int EPI>
__global__ void __launch_bounds__(128, 2) mma_gemm(
    const u16* __restrict__ Ahi, const u16* __restrict__ Alo, size_t aStride,
    const u16* __restrict__ Bhi, const u16* __restrict__ Blo,
    const float* __restrict__ bias,
    float* __restrict__ Cf, u16* __restrict__ Chi, u16* __restrict__ Clo,
    size_t cStride, int K)
{
    extern __shared__ char sm[];
    const u32 sb = smem_u32(sm);

    const int tid  = threadIdx.x;
    const int wid  = tid >> 5;
    const int lane = tid & 31;
    const int wm   = wid & 1;       // 2 warps in M, 64 rows each
    const int wn   = wid >> 1;      // 2 warps in N, 64 cols each
    const int m0   = blockIdx.y * 128;
    const int n0   = blockIdx.x * 128;
    const int e    = blockIdx.z;
    const int N    = gridDim.x * 128;

    const size_t wOff = (size_t)e * HID * INTER;
    const u16* srcs[4] = { Ahi + (size_t)e * aStride + (size_t)m0 * K,
                           Alo + (size_t)e * aStride + (size_t)m0 * K,
                           Bhi + wOff + (size_t)n0 * K,
                           Blo + wOff + (size_t)n0 * K };
    bias += (size_t)e * N;

    // ldmatrix lane decomposition
    const u32 a_r  = lane & 15;           // row within 16
    const u32 a_cs = lane >> 4;           // k-chunk select
    const u32 b_r  = (lane & 7) + (((u32)lane >> 4) & 1) * 8;
    const u32 b_cs = ((u32)lane >> 3) & 1;

    float acc[4][8][4];
#pragma unroll
    for (int i = 0; i < 4; i++)
#pragma unroll
        for (int j = 0; j < 8; j++)
#pragma unroll
            for (int q = 0; q < 4; q++) acc[i][j][q] = 0.f;

    const int nst = K / 32;

    // stage loader: 2048 cp16 (A 1024 + B 1024) / 128 threads = 16 each
    auto load_stage = [&](int buf, int k0) {
        u32 dbase = sb + (u32)buf * STAGEB;
#pragma unroll
        for (int i = 0; i < 16; i++) {
            int idx = tid + i * 128;
            int t   = idx >> 10;            // 0 = A tile, 1 = B tile
            int j   = idx & 1023;
            int row = j >> 3, c = j & 7;    // c<4: hi chunks, c>=4: lo chunks
            const u16* s = srcs[t * 2 + (c >> 2)] + (size_t)row * K + k0 + (c & 3) * 8;
            cp16(dbase + (u32)t * 16384 + swz((u32)row, (u32)c), s);
        }
        asm volatile("cp.async.commit_group;" ::: "memory");
    };

    load_stage(0, 0);
    load_stage(1, 32);

    int buf = 0;
    for (int s = 0; s < nst; s++) {
        if (s + 1 < nst) asm volatile("cp.async.wait_group 1;" ::: "memory");
        else             asm volatile("cp.async.wait_group 0;" ::: "memory");
        __syncthreads();
        if (s + 2 < nst) load_stage((s + 2) % NSTAGE, (s + 2) * 32);

        const u32 aT = sb + (u32)buf * STAGEB;
        const u32 bT = aT + 16384;

#pragma unroll
        for (int ks = 0; ks < 2; ks++) {
            const u32 cHi = (u32)ks * 2;          // hi chunks: cHi + cs
            u32 ah[4][4], al[4][4];
#pragma unroll
            for (int mf = 0; mf < 4; mf++) {
                u32 row = (u32)(wm * 64 + mf * 16) + a_r;
                ldm_x4(ah[mf][0], ah[mf][1], ah[mf][2], ah[mf][3],
                       aT + swz(row, cHi + a_cs));
                ldm_x4(al[mf][0], al[mf][1], al[mf][2], al[mf][3],
                       aT + swz(row, cHi + a_cs + 4));
            }
#pragma unroll
            for (int np = 0; np < 4; np++) {       // 4 pairs of n8 frags
                u32 bh0[2], bh1[2], bl0[2], bl1[2];
                u32 row = (u32)(wn * 64 + np * 16) + b_r;
                ldm_x4(bh0[0], bh0[1], bh1[0], bh1[1], bT + swz(row, cHi + b_cs));
                ldm_x4(bl0[0], bl0[1], bl1[0], bl1[1], bT + swz(row, cHi + b_cs + 4));
#pragma unroll
                for (int mf = 0; mf < 4; mf++) {
                    mma_bf16(acc[mf][np * 2 + 0], ah[mf], bh0);
                    mma_bf16(acc[mf][np * 2 + 1], ah[mf], bh1);
                    mma_bf16(acc[mf][np * 2 + 0], ah[mf], bl0);
                    mma_bf16(acc[mf][np * 2 + 1], ah[mf], bl1);
                    mma_bf16(acc[mf][np * 2 + 0], al[mf], bh0);
                    mma_bf16(acc[mf][np * 2 + 1], al[mf], bh1);
                }
            }
        }
        buf = (buf + 1 == NSTAGE) ? 0 : buf + 1;
    }

    // ---- epilogue ----
    u16* ChiE = Chi;  u16* CloE = Clo;  float* CfE = Cf;
    if (EPI == 0) { ChiE += (size_t)e * cStride; CloE += (size_t)e * cStride; }
    else          { CfE  += (size_t)e * cStride; }

    const int g  = lane >> 2;
    const int tg = lane & 3;
#pragma unroll
    for (int mf = 0; mf < 4; mf++) {
#pragma unroll
        for (int half = 0; half < 2; half++) {
            int r = m0 + wm * 64 + mf * 16 + g + half * 8;
#pragma unroll
            for (int nf = 0; nf < 8; nf++) {
                int c = n0 + wn * 64 + nf * 8 + tg * 2;
                float v0 = acc[mf][nf][half * 2 + 0] + bias[c];
                float v1 = acc[mf][nf][half * 2 + 1] + bias[c + 1];
                if (EPI == 0) {
                    u16 h0, l0, h1, l1;
                    split2(gelu_exact(v0), h0, l0);
                    split2(gelu_exact(v1), h1, l1);
                    *reinterpret_cast<u32*>(ChiE + (size_t)r * N + c) =
                        (u32)h0 | ((u32)h1 << 16);
                    *reinterpret_cast<u32*>(CloE + (size_t)r * N + c) =
                        (u32)l0 | ((u32)l1 << 16);
                } else {
                    *reinterpret_cast<float2*>(CfE + (size_t)r * N + c) =
                        make_float2(v0, v1);
                }
            }
        }
    }
}

// ---------------------------------------------------------------------------
extern "C" void kernel_launch(void* const* d_in, const int* in_sizes, int n_in,
                              void* d_out, int out_size) {
    const float* x  = (const float*)d_in[0];
    const float* Wg = (const float*)d_in[1];
    const float* W1 = (const float*)d_in[2];
    const float* b1 = (const float*)d_in[3];
    const float* W2 = (const float*)d_in[4];
    const float* b2 = (const float*)d_in[5];
    float* out = (float*)d_out;

    u16 *xhi, *xlo, *w1hi, *w1lo, *w2hi, *w2lo, *hhi, *hlo;
    float *gbuf, *ybuf;
    cudaGetSymbolAddress((void**)&xhi, g_xhi);
    cudaGetSymbolAddress((void**)&xlo, g_xlo);
    cudaGetSymbolAddress((void**)&w1hi, g_w1hi);
    cudaGetSymbolAddress((void**)&w1lo, g_w1lo);
    cudaGetSymbolAddress((void**)&w2hi, g_w2hi);
    cudaGetSymbolAddress((void**)&w2lo, g_w2lo);
    cudaGetSymbolAddress((void**)&hhi, g_hhi);
    cudaGetSymbolAddress((void**)&hlo, g_hlo);
    cudaGetSymbolAddress((void**)&gbuf, g_gate);
    cudaGetSymbolAddress((void**)&ybuf, g_y);

    cudaFuncSetAttribute(mma_gemm<0>, cudaFuncAttributeMaxDynamicSharedMemorySize, SM_BYTES);
    cudaFuncSetAttribute(mma_gemm<1>, cudaFuncAttributeMaxDynamicSharedMemorySize, SM_BYTES);

    gate_kernel<<<T_TOK / 8, 256>>>(x, Wg, gbuf);

    size_t n4x = (size_t)T_TOK * HID / 4;
    split_kernel<<<(unsigned)((n4x + 255) / 256), 256>>>(x, xhi, xlo, n4x);
    tsplit_kernel<<<dim3(INTER / 32, HID / 64, NEXP), dim3(32, 8)>>>(W1, w1hi, w1lo, HID, INTER);
    tsplit_kernel<<<dim3(HID / 32, INTER / 64, NEXP), dim3(32, 8)>>>(W2, w2hi, w2lo, INTER, HID);

    // GEMM1 all experts: M=T, N=INTER, K=HID
    mma_gemm<0><<<dim3(INTER / 128, T_TOK / 128, NEXP), 128, SM_BYTES>>>(
        xhi, xlo, 0, w1hi, w1lo, b1,
        nullptr, hhi, hlo, (size_t)T_TOK * INTER, HID);

    // GEMM2 all experts: M=T, N=HID, K=INTER
    mma_gemm<1><<<dim3(HID / 128, T_TOK / 128, NEXP), 128, SM_BYTES>>>(
        hhi, hlo, (size_t)T_TOK * INTER, w2hi, w2lo, b2,
        ybuf, nullptr, nullptr, (size_t)T_TOK * HID, INTER);

    // out = sum_e gate[t,e] * y[e]
    size_t n4o = (size_t)T_TOK * HID / 4;
    reduce_kernel<<<(unsigned)((n4o + 255) / 256), 256>>>(ybuf, gbuf, out);
}

// round 9
// speedup vs baseline: 4.3302x; 1.3315x over previous
#include <cuda_runtime.h>
#include <cuda_bf16.h>
#include <cstdint>

#define T_TOK 4096
#define HID   1024
#define INTER 4096
#define NEXP  8

typedef unsigned short u16;
typedef unsigned int   u32;
typedef unsigned long long u64;

// ---------------------------------------------------------------------------
// Device scratch (tf32-in-u32 operands)
// ---------------------------------------------------------------------------
__device__ u32 g_xt[(size_t)T_TOK * HID];            // tf32 x [T][H]
__device__ u32 g_w1t[(size_t)NEXP * HID * INTER];    // [E][I][H] transposed tf32
__device__ u32 g_w2t[(size_t)NEXP * HID * INTER];    // [E][H][I] transposed tf32
__device__ u32 g_ht[(size_t)NEXP * T_TOK * INTER];   // per-expert h tf32
__device__ float g_y[(size_t)NEXP * T_TOK * HID];    // per-expert y fp32
__device__ float g_gate[T_TOK * NEXP];

// ---------------------------------------------------------------------------
// Helpers
// ---------------------------------------------------------------------------
__device__ __forceinline__ u32 smem_u32(const void* p) {
    u32 a;
    asm("{ .reg .u64 t; cvta.to.shared.u64 t, %1; cvt.u32.u64 %0, t; }"
        : "=r"(a) : "l"(p));
    return a;
}
__device__ __forceinline__ void cp16(u32 dst, const void* src) {
    asm volatile("cp.async.cg.shared.global [%0], [%1], 16;"
                 :: "r"(dst), "l"(src));
}
__device__ __forceinline__ void ldm_x4(u32& r0, u32& r1, u32& r2, u32& r3, u32 a) {
    asm volatile("ldmatrix.sync.aligned.m8n8.x4.shared.b16 {%0,%1,%2,%3}, [%4];"
                 : "=r"(r0), "=r"(r1), "=r"(r2), "=r"(r3) : "r"(a));
}
__device__ __forceinline__ void mma_tf32(float* c, const u32* a, const u32* b) {
    asm volatile("mma.sync.aligned.m16n8k8.row.col.f32.tf32.tf32.f32 "
                 "{%0,%1,%2,%3}, {%4,%5,%6,%7}, {%8,%9}, {%0,%1,%2,%3};"
                 : "+f"(c[0]), "+f"(c[1]), "+f"(c[2]), "+f"(c[3])
                 : "r"(a[0]), "r"(a[1]), "r"(a[2]), "r"(a[3]),
                   "r"(b[0]), "r"(b[1]));
}
__device__ __forceinline__ u32 to_tf32(float f) {
    u32 r;
    asm("cvt.rna.tf32.f32 %0, %1;" : "=r"(r) : "f"(f));
    return r;
}
__device__ __forceinline__ float gelu_exact(float v) { return v * normcdff(v); }

// ---------------------------------------------------------------------------
// Gate: logits = x @ Wg^T, softmax over E=8. One warp per token.
// ---------------------------------------------------------------------------
__global__ void gate_kernel(const float* __restrict__ x,
                            const float* __restrict__ Wg,
                            float* __restrict__ gate) {
    int warp = (blockIdx.x * blockDim.x + threadIdx.x) >> 5;
    int lane = threadIdx.x & 31;
    if (warp >= T_TOK) return;
    const float* xr = x + (size_t)warp * HID;
    float acc[NEXP];
#pragma unroll
    for (int e = 0; e < NEXP; e++) acc[e] = 0.f;
    for (int k = lane; k < HID; k += 32) {
        float xv = xr[k];
#pragma unroll
        for (int e = 0; e < NEXP; e++) acc[e] = fmaf(xv, Wg[e * HID + k], acc[e]);
    }
#pragma unroll
    for (int e = 0; e < NEXP; e++)
#pragma unroll
        for (int off = 16; off > 0; off >>= 1)
            acc[e] += __shfl_xor_sync(0xffffffffu, acc[e], off);
    if (lane == 0) {
        float mx = acc[0];
#pragma unroll
        for (int e = 1; e < NEXP; e++) mx = fmaxf(mx, acc[e]);
        float s = 0.f;
#pragma unroll
        for (int e = 0; e < NEXP; e++) { acc[e] = expf(acc[e] - mx); s += acc[e]; }
        float inv = 1.f / s;
#pragma unroll
        for (int e = 0; e < NEXP; e++) gate[warp * NEXP + e] = acc[e] * inv;
    }
}

// ---------------------------------------------------------------------------
// x fp32 -> tf32 (rna), layout preserved
// ---------------------------------------------------------------------------
__global__ void xcvt_kernel(const float* __restrict__ in, u32* __restrict__ out,
                            size_t n4) {
    size_t i = (size_t)blockIdx.x * blockDim.x + threadIdx.x;
    if (i >= n4) return;
    float4 v = reinterpret_cast<const float4*>(in)[i];
    uint4 o;
    o.x = to_tf32(v.x); o.y = to_tf32(v.y);
    o.z = to_tf32(v.z); o.w = to_tf32(v.w);
    reinterpret_cast<uint4*>(out)[i] = o;
}

// ---------------------------------------------------------------------------
// W [E][R][C] fp32 -> transposed tf32 [E][C][R]
// ---------------------------------------------------------------------------
__global__ void tcvt_kernel(const float* __restrict__ W, u32* __restrict__ outT,
                            int R, int C) {
    __shared__ float t[64][33];
    int e = blockIdx.z;
    const float* Win = W + (size_t)e * R * C;
    u32* oT = outT + (size_t)e * R * C;
    int c0 = blockIdx.x * 32, r0 = blockIdx.y * 64;
    int tx = threadIdx.x, ty = threadIdx.y;  // (32, 8)
#pragma unroll
    for (int i = 0; i < 8; i++)
        t[ty + i * 8][tx] = Win[(size_t)(r0 + ty + i * 8) * C + c0 + tx];
    __syncthreads();
#pragma unroll
    for (int i = 0; i < 4; i++) {
        int crow = ty + i * 8;
        uint2 o;
        o.x = to_tf32(t[2 * tx + 0][crow]);
        o.y = to_tf32(t[2 * tx + 1][crow]);
        size_t off = (size_t)(c0 + crow) * R + r0 + 2 * tx;
        *reinterpret_cast<uint2*>(oT + off) = o;
    }
}

// ---------------------------------------------------------------------------
// Final reduce: out[t,h] = sum_e gate[t,e] * y[e,t,h]
// ---------------------------------------------------------------------------
__global__ void reduce_kernel(const float* __restrict__ y,
                              const float* __restrict__ gate,
                              float* __restrict__ out) {
    size_t idx = (size_t)blockIdx.x * blockDim.x + threadIdx.x;  // over T*H/4
    if (idx >= (size_t)T_TOK * HID / 4) return;
    int t = (int)(idx / (HID / 4));
    float4 s = make_float4(0.f, 0.f, 0.f, 0.f);
#pragma unroll
    for (int e = 0; e < NEXP; e++) {
        float g = gate[t * NEXP + e];
        float4 v = reinterpret_cast<const float4*>(y + (size_t)e * T_TOK * HID)[idx];
        s.x = fmaf(g, v.x, s.x); s.y = fmaf(g, v.y, s.y);
        s.z = fmaf(g, v.z, s.z); s.w = fmaf(g, v.w, s.w);
    }
    reinterpret_cast<float4*>(out)[idx] = s;
}

// ---------------------------------------------------------------------------
// TF32 mma.sync GEMM over grid.z experts: C = A[M,K] @ B[N,K]^T
// 128x128 CTA tile, BK=32 floats, 128 threads (4 warps, 64x64 warp tiles),
// 128B XOR-swizzled rows, 3-stage cp.async ring, 1 sync/stage, 2 CTAs/SM.
// EPI 0: h = tf32(gelu(. + b)); EPI 1: y = . + b (fp32)
// ---------------------------------------------------------------------------
#define STAGEB 32768                     // A(16K) + B(16K) per stage
#define NSTAGE 3
#define SM_BYTES (NSTAGE * STAGEB)       // 98304 -> 2 CTAs/SM

__device__ __forceinline__ u32 swz(u32 row, u32 ch) {   // byte offset, 128B rows
    return row * 128 + ((ch ^ (row & 7)) << 4);
}

template <int EPI>
__global__ void __launch_bounds__(128, 2) mma_gemm(
    const u32* __restrict__ At, size_t aStride,
    const u32* __restrict__ Bt,
    const float* __restrict__ bias,
    float* __restrict__ Cf, u32* __restrict__ Ct,
    size_t cStride, int K)
{
    extern __shared__ char sm[];
    const u32 sb = smem_u32(sm);

    const int tid  = threadIdx.x;
    const int wid  = tid >> 5;
    const int lane = tid & 31;
    const int wm   = wid & 1;       // 2 warps in M, 64 rows each
    const int wn   = wid >> 1;      // 2 warps in N, 64 cols each
    const int m0   = blockIdx.y * 128;
    const int n0   = blockIdx.x * 128;
    const int e    = blockIdx.z;
    const int N    = gridDim.x * 128;

    const u32* srcA = At + (size_t)e * aStride + (size_t)m0 * K;
    const u32* srcB = Bt + (size_t)e * HID * INTER + (size_t)n0 * K;
    bias += (size_t)e * N;

    // ldmatrix lane decomposition: g = block group, lr = row within 8
    const u32 g  = (u32)lane >> 3;
    const u32 lr = (u32)lane & 7;
    const u32 a_row = lr + ((g & 1) << 3);     // A: blocks m0-7/m8-15 x k-chunks
    const u32 a_ch  = g >> 1;
    const u32 b_row = lr + ((g >> 1) << 3);    // B: blocks n0-7/n8-15 x k-chunks
    const u32 b_ch  = g & 1;

    float acc[4][8][4];
#pragma unroll
    for (int i = 0; i < 4; i++)
#pragma unroll
        for (int j = 0; j < 8; j++)
#pragma unroll
            for (int q = 0; q < 4; q++) acc[i][j][q] = 0.f;

    const int nst = K / 32;

    // stage loader: 2048 16B-chunks (A 1024 + B 1024) / 128 threads = 16 each
    auto load_stage = [&](int buf, int k0) {
        u32 dbase = sb + (u32)buf * STAGEB;
#pragma unroll
        for (int i = 0; i < 16; i++) {
            int idx = tid + i * 128;
            int t   = idx >> 10;            // 0 = A tile, 1 = B tile
            int j   = idx & 1023;
            int row = j >> 3, c = j & 7;    // chunk c = 4 tf32 at k0 + c*4
            const u32* s = (t ? srcB : srcA) + (size_t)row * K + k0 + c * 4;
            cp16(dbase + (u32)t * 16384 + swz((u32)row, (u32)c), s);
        }
        asm volatile("cp.async.commit_group;" ::: "memory");
    };

    load_stage(0, 0);
    load_stage(1, 32);

    int buf = 0;
    for (int s = 0; s < nst; s++) {
        if (s + 1 < nst) asm volatile("cp.async.wait_group 1;" ::: "memory");
        else             asm volatile("cp.async.wait_group 0;" ::: "memory");
        __syncthreads();
        if (s + 2 < nst) load_stage((s + 2) % NSTAGE, (s + 2) * 32);

        const u32 aT = sb + (u32)buf * STAGEB;
        const u32 bT = aT + 16384;

#pragma unroll
        for (int ks = 0; ks < 4; ks++) {            // 4 x k8 per stage
            const u32 cB = (u32)ks * 2;             // 2 chunks per k8
            u32 af[4][4];
#pragma unroll
            for (int mf = 0; mf < 4; mf++) {
                u32 row = (u32)(wm * 64 + mf * 16) + a_row;
                ldm_x4(af[mf][0], af[mf][1], af[mf][2], af[mf][3],
                       aT + swz(row, cB + a_ch));
            }
            u32 bf[8][2];
#pragma unroll
            for (int bp = 0; bp < 4; bp++) {        // each covers 2 n8 frags
                u32 row = (u32)(wn * 64 + bp * 16) + b_row;
                ldm_x4(bf[bp * 2][0], bf[bp * 2][1],
                       bf[bp * 2 + 1][0], bf[bp * 2 + 1][1],
                       bT + swz(row, cB + b_ch));
            }
#pragma unroll
            for (int mf = 0; mf < 4; mf++)
#pragma unroll
                for (int nf = 0; nf < 8; nf++)
                    mma_tf32(acc[mf][nf], af[mf], bf[nf]);
        }
        buf = (buf + 1 == NSTAGE) ? 0 : buf + 1;
    }

    // ---- epilogue ----
    u32*   CtE = Ct + (EPI == 0 ? (size_t)e * cStride : 0);
    float* CfE = Cf + (EPI == 1 ? (size_t)e * cStride : 0);

    const int gr = lane >> 2;
    const int tg = lane & 3;
#pragma unroll
    for (int mf = 0; mf < 4; mf++) {
#pragma unroll
        for (int half = 0; half < 2; half++) {
            int r = m0 + wm * 64 + mf * 16 + gr + half * 8;
#pragma unroll
            for (int nf = 0; nf < 8; nf++) {
                int c = n0 + wn * 64 + nf * 8 + tg * 2;
                float v0 = acc[mf][nf][half * 2 + 0] + bias[c];
                float v1 = acc[mf][nf][half * 2 + 1] + bias[c + 1];
                if (EPI == 0) {
                    uint2 o;
                    o.x = to_tf32(gelu_exact(v0));
                    o.y = to_tf32(gelu_exact(v1));
                    *reinterpret_cast<uint2*>(CtE + (size_t)r * N + c) = o;
                } else {
                    *reinterpret_cast<float2*>(CfE + (size_t)r * N + c) =
                        make_float2(v0, v1);
                }
            }
        }
    }
}

// ---------------------------------------------------------------------------
extern "C" void kernel_launch(void* const* d_in, const int* in_sizes, int n_in,
                              void* d_out, int out_size) {
    const float* x  = (const float*)d_in[0];
    const float* Wg = (const float*)d_in[1];
    const float* W1 = (const float*)d_in[2];
    const float* b1 = (const float*)d_in[3];
    const float* W2 = (const float*)d_in[4];
    const float* b2 = (const float*)d_in[5];
    float* out = (float*)d_out;

    u32 *xt, *w1t, *w2t, *ht;
    float *gbuf, *ybuf;
    cudaGetSymbolAddress((void**)&xt, g_xt);
    cudaGetSymbolAddress((void**)&w1t, g_w1t);
    cudaGetSymbolAddress((void**)&w2t, g_w2t);
    cudaGetSymbolAddress((void**)&ht, g_ht);
    cudaGetSymbolAddress((void**)&gbuf, g_gate);
    cudaGetSymbolAddress((void**)&ybuf, g_y);

    cudaFuncSetAttribute(mma_gemm<0>, cudaFuncAttributeMaxDynamicSharedMemorySize, SM_BYTES);
    cudaFuncSetAttribute(mma_gemm<1>, cudaFuncAttributeMaxDynamicSharedMemorySize, SM_BYTES);

    gate_kernel<<<T_TOK / 8, 256>>>(x, Wg, gbuf);

    size_t n4x = (size_t)T_TOK * HID / 4;
    xcvt_kernel<<<(unsigned)((n4x + 255) / 256), 256>>>(x, xt, n4x);
    tcvt_kernel<<<dim3(INTER / 32, HID / 64, NEXP), dim3(32, 8)>>>(W1, w1t, HID, INTER);
    tcvt_kernel<<<dim3(HID / 32, INTER / 64, NEXP), dim3(32, 8)>>>(W2, w2t, INTER, HID);

    // GEMM1 all experts: M=T, N=INTER, K=HID
    mma_gemm<0><<<dim3(INTER / 128, T_TOK / 128, NEXP), 128, SM_BYTES>>>(
        xt, 0, w1t, b1, nullptr, ht, (size_t)T_TOK * INTER, HID);

    // GEMM2 all experts: M=T, N=HID, K=INTER
    mma_gemm<1><<<dim3(HID / 128, T_TOK / 128, NEXP), 128, SM_BYTES>>>(
        ht, (size_t)T_TOK * INTER, w2t, b2, ybuf, nullptr,
        (size_t)T_TOK * HID, INTER);

    // out = sum_e gate[t,e] * y[e]
    size_t n4o = (size_t)T_TOK * HID / 4;
    reduce_kernel<<<(unsigned)((n4o + 255) / 256), 256>>>(ybuf, gbuf, out);
}

// round 10
// speedup vs baseline: 7.3033x; 1.6866x over previous
#include <cuda_runtime.h>
#include <cuda_fp16.h>
#include <cstdint>

#define T_TOK 4096
#define HID   1024
#define INTER 4096
#define NEXP  8

typedef unsigned short u16;
typedef unsigned int   u32;
typedef unsigned long long u64;

// ---------------------------------------------------------------------------
// Device scratch (fp16 operands)
// ---------------------------------------------------------------------------
__device__ u16 g_xh[(size_t)T_TOK * HID];            // fp16 x [T][H]
__device__ u16 g_w1h[(size_t)NEXP * HID * INTER];    // [E][I][H] transposed fp16
__device__ u16 g_w2h[(size_t)NEXP * HID * INTER];    // [E][H][I] transposed fp16
__device__ u16 g_hh[(size_t)NEXP * T_TOK * INTER];   // per-expert h fp16
__device__ float g_y[(size_t)NEXP * T_TOK * HID];    // per-expert y fp32
__device__ float g_gate[T_TOK * NEXP];

// ---------------------------------------------------------------------------
// Helpers
// ---------------------------------------------------------------------------
__device__ __forceinline__ u32 smem_u32(const void* p) {
    u32 a;
    asm("{ .reg .u64 t; cvta.to.shared.u64 t, %1; cvt.u32.u64 %0, t; }"
        : "=r"(a) : "l"(p));
    return a;
}
__device__ __forceinline__ void cp16(u32 dst, const void* src) {
    asm volatile("cp.async.cg.shared.global [%0], [%1], 16;"
                 :: "r"(dst), "l"(src));
}
__device__ __forceinline__ void ldm_x4(u32& r0, u32& r1, u32& r2, u32& r3, u32 a) {
    asm volatile("ldmatrix.sync.aligned.m8n8.x4.shared.b16 {%0,%1,%2,%3}, [%4];"
                 : "=r"(r0), "=r"(r1), "=r"(r2), "=r"(r3) : "r"(a));
}
__device__ __forceinline__ void mma_f16(float* c, const u32* a, const u32* b) {
    asm volatile("mma.sync.aligned.m16n8k16.row.col.f32.f16.f16.f32 "
                 "{%0,%1,%2,%3}, {%4,%5,%6,%7}, {%8,%9}, {%0,%1,%2,%3};"
                 : "+f"(c[0]), "+f"(c[1]), "+f"(c[2]), "+f"(c[3])
                 : "r"(a[0]), "r"(a[1]), "r"(a[2]), "r"(a[3]),
                   "r"(b[0]), "r"(b[1]));
}
__device__ __forceinline__ float gelu_exact(float v) { return v * normcdff(v); }

// ---------------------------------------------------------------------------
// Gate: logits = x @ Wg^T, softmax over E=8. One warp per token.
// ---------------------------------------------------------------------------
__global__ void gate_kernel(const float* __restrict__ x,
                            const float* __restrict__ Wg,
                            float* __restrict__ gate) {
    int warp = (blockIdx.x * blockDim.x + threadIdx.x) >> 5;
    int lane = threadIdx.x & 31;
    if (warp >= T_TOK) return;
    const float* xr = x + (size_t)warp * HID;
    float acc[NEXP];
#pragma unroll
    for (int e = 0; e < NEXP; e++) acc[e] = 0.f;
    for (int k = lane; k < HID; k += 32) {
        float xv = xr[k];
#pragma unroll
        for (int e = 0; e < NEXP; e++) acc[e] = fmaf(xv, Wg[e * HID + k], acc[e]);
    }
#pragma unroll
    for (int e = 0; e < NEXP; e++)
#pragma unroll
        for (int off = 16; off > 0; off >>= 1)
            acc[e] += __shfl_xor_sync(0xffffffffu, acc[e], off);
    if (lane == 0) {
        float mx = acc[0];
#pragma unroll
        for (int e = 1; e < NEXP; e++) mx = fmaxf(mx, acc[e]);
        float s = 0.f;
#pragma unroll
        for (int e = 0; e < NEXP; e++) { acc[e] = expf(acc[e] - mx); s += acc[e]; }
        float inv = 1.f / s;
#pragma unroll
        for (int e = 0; e < NEXP; e++) gate[warp * NEXP + e] = acc[e] * inv;
    }
}

// ---------------------------------------------------------------------------
// x fp32 -> fp16, layout preserved
// ---------------------------------------------------------------------------
__global__ void xcvt_kernel(const float* __restrict__ in, u16* __restrict__ out,
                            size_t n4) {
    size_t i = (size_t)blockIdx.x * blockDim.x + threadIdx.x;
    if (i >= n4) return;
    float4 v = reinterpret_cast<const float4*>(in)[i];
    __half h[4];
    h[0] = __float2half_rn(v.x); h[1] = __float2half_rn(v.y);
    h[2] = __float2half_rn(v.z); h[3] = __float2half_rn(v.w);
    reinterpret_cast<u64*>(out)[i] = *reinterpret_cast<u64*>(h);
}

// ---------------------------------------------------------------------------
// W [E][R][C] fp32 -> transposed fp16 [E][C][R]
// ---------------------------------------------------------------------------
__global__ void tcvt_kernel(const float* __restrict__ W, u16* __restrict__ outT,
                            int R, int C) {
    __shared__ float t[64][33];
    int e = blockIdx.z;
    const float* Win = W + (size_t)e * R * C;
    u16* oT = outT + (size_t)e * R * C;
    int c0 = blockIdx.x * 32, r0 = blockIdx.y * 64;
    int tx = threadIdx.x, ty = threadIdx.y;  // (32, 8)
#pragma unroll
    for (int i = 0; i < 8; i++)
        t[ty + i * 8][tx] = Win[(size_t)(r0 + ty + i * 8) * C + c0 + tx];
    __syncthreads();
#pragma unroll
    for (int i = 0; i < 4; i++) {
        int crow = ty + i * 8;
        __half h0 = __float2half_rn(t[2 * tx + 0][crow]);
        __half h1 = __float2half_rn(t[2 * tx + 1][crow]);
        size_t off = (size_t)(c0 + crow) * R + r0 + 2 * tx;
        *reinterpret_cast<u32*>(oT + off) =
            (u32)__half_as_ushort(h0) | ((u32)__half_as_ushort(h1) << 16);
    }
}

// ---------------------------------------------------------------------------
// Final reduce: out[t,h] = sum_e gate[t,e] * y[e,t,h]
// ---------------------------------------------------------------------------
__global__ void reduce_kernel(const float* __restrict__ y,
                              const float* __restrict__ gate,
                              float* __restrict__ out) {
    size_t idx = (size_t)blockIdx.x * blockDim.x + threadIdx.x;  // over T*H/4
    if (idx >= (size_t)T_TOK * HID / 4) return;
    int t = (int)(idx / (HID / 4));
    float4 s = make_float4(0.f, 0.f, 0.f, 0.f);
#pragma unroll
    for (int e = 0; e < NEXP; e++) {
        float g = gate[t * NEXP + e];
        float4 v = reinterpret_cast<const float4*>(y + (size_t)e * T_TOK * HID)[idx];
        s.x = fmaf(g, v.x, s.x); s.y = fmaf(g, v.y, s.y);
        s.z = fmaf(g, v.z, s.z); s.w = fmaf(g, v.w, s.w);
    }
    reinterpret_cast<float4*>(out)[idx] = s;
}

// ---------------------------------------------------------------------------
// FP16 mma.sync GEMM over grid.z experts: C = A[M,K] @ B[N,K]^T (fp32 accum)
// 128x128 CTA tile, BK=64 halves (128B rows), 128 threads (4 warps, 64x64
// warp tiles), XOR-swizzled SMEM, 3-stage cp.async ring, 1 sync/stage,
// 2 CTAs/SM. EPI 0: h = fp16(gelu(. + b)); EPI 1: y = . + b (fp32)
// ---------------------------------------------------------------------------
#define STAGEB 32768                     // A(16K) + B(16K) per stage
#define NSTAGE 3
#define SM_BYTES (NSTAGE * STAGEB)       // 98304 -> 2 CTAs/SM

__device__ __forceinline__ u32 swz(u32 row, u32 ch) {   // byte offset, 128B rows
    return row * 128 + ((ch ^ (row & 7)) << 4);
}

template <int EPI>
__global__ void __launch_bounds__(128, 2) mma_gemm(
    const u16* __restrict__ Ah, size_t aStride,
    const u16* __restrict__ Bh,
    const float* __restrict__ bias,
    float* __restrict__ Cf, u16* __restrict__ Ch,
    size_t cStride, int K)
{
    extern __shared__ char sm[];
    const u32 sb = smem_u32(sm);

    const int tid  = threadIdx.x;
    const int wid  = tid >> 5;
    const int lane = tid & 31;
    const int wm   = wid & 1;       // 2 warps in M, 64 rows each
    const int wn   = wid >> 1;      // 2 warps in N, 64 cols each
    const int m0   = blockIdx.y * 128;
    const int n0   = blockIdx.x * 128;
    const int e    = blockIdx.z;
    const int N    = gridDim.x * 128;

    const u16* srcA = Ah + (size_t)e * aStride + (size_t)m0 * K;
    const u16* srcB = Bh + (size_t)e * HID * INTER + (size_t)n0 * K;
    bias += (size_t)e * N;

    // ldmatrix lane addressing (b16 fragments)
    const u32 a_r  = lane & 15;           // row within 16
    const u32 a_cs = lane >> 4;           // k-chunk select (2 chunks per k16)
    const u32 b_r  = (lane & 7) + (((u32)lane >> 4) & 1) * 8;
    const u32 b_cs = ((u32)lane >> 3) & 1;

    float acc[4][8][4];
#pragma unroll
    for (int i = 0; i < 4; i++)
#pragma unroll
        for (int j = 0; j < 8; j++)
#pragma unroll
            for (int q = 0; q < 4; q++) acc[i][j][q] = 0.f;

    const int nst = K / 64;

    // stage loader: 2048 16B-chunks (A 1024 + B 1024) / 128 threads = 16 each
    auto load_stage = [&](int buf, int k0) {
        u32 dbase = sb + (u32)buf * STAGEB;
#pragma unroll
        for (int i = 0; i < 16; i++) {
            int idx = tid + i * 128;
            int t   = idx >> 10;            // 0 = A tile, 1 = B tile
            int j   = idx & 1023;
            int row = j >> 3, c = j & 7;    // chunk c = 8 halves at k0 + c*8
            const u16* s = (t ? srcB : srcA) + (size_t)row * K + k0 + c * 8;
            cp16(dbase + (u32)t * 16384 + swz((u32)row, (u32)c), s);
        }
        asm volatile("cp.async.commit_group;" ::: "memory");
    };

    load_stage(0, 0);
    load_stage(1, 64);

    int buf = 0;
    for (int s = 0; s < nst; s++) {
        if (s + 1 < nst) asm volatile("cp.async.wait_group 1;" ::: "memory");
        else             asm volatile("cp.async.wait_group 0;" ::: "memory");
        __syncthreads();
        if (s + 2 < nst) load_stage((s + 2) % NSTAGE, (s + 2) * 64);

        const u32 aT = sb + (u32)buf * STAGEB;
        const u32 bT = aT + 16384;

#pragma unroll
        for (int ks = 0; ks < 4; ks++) {            // 4 x k16 per stage
            const u32 cB = (u32)ks * 2;             // 2 chunks per k16
            u32 af[4][4];
#pragma unroll
            for (int mf = 0; mf < 4; mf++) {
                u32 row = (u32)(wm * 64 + mf * 16) + a_r;
                ldm_x4(af[mf][0], af[mf][1], af[mf][2], af[mf][3],
                       aT + swz(row, cB + a_cs));
            }
            u32 bf[8][2];
#pragma unroll
            for (int bp = 0; bp < 4; bp++) {        // each covers 2 n8 frags
                u32 row = (u32)(wn * 64 + bp * 16) + b_r;
                ldm_x4(bf[bp * 2][0], bf[bp * 2][1],
                       bf[bp * 2 + 1][0], bf[bp * 2 + 1][1],
                       bT + swz(row, cB + b_cs));
            }
#pragma unroll
            for (int mf = 0; mf < 4; mf++)
#pragma unroll
                for (int nf = 0; nf < 8; nf++)
                    mma_f16(acc[mf][nf], af[mf], bf[nf]);
        }
        buf = (buf + 1 == NSTAGE) ? 0 : buf + 1;
    }

    // ---- epilogue ----
    u16*   ChE = Ch + (EPI == 0 ? (size_t)e * cStride : 0);
    float* CfE = Cf + (EPI == 1 ? (size_t)e * cStride : 0);

    const int gr = lane >> 2;
    const int tg = lane & 3;
#pragma unroll
    for (int mf = 0; mf < 4; mf++) {
#pragma unroll
        for (int half = 0; half < 2; half++) {
            int r = m0 + wm * 64 + mf * 16 + gr + half * 8;
#pragma unroll
            for (int nf = 0; nf < 8; nf++) {
                int c = n0 + wn * 64 + nf * 8 + tg * 2;
                float v0 = acc[mf][nf][half * 2 + 0] + bias[c];
                float v1 = acc[mf][nf][half * 2 + 1] + bias[c + 1];
                if (EPI == 0) {
                    __half h0 = __float2half_rn(gelu_exact(v0));
                    __half h1 = __float2half_rn(gelu_exact(v1));
                    *reinterpret_cast<u32*>(ChE + (size_t)r * N + c) =
                        (u32)__half_as_ushort(h0) |
                        ((u32)__half_as_ushort(h1) << 16);
                } else {
                    *reinterpret_cast<float2*>(CfE + (size_t)r * N + c) =
                        make_float2(v0, v1);
                }
            }
        }
    }
}

// ---------------------------------------------------------------------------
extern "C" void kernel_launch(void* const* d_in, const int* in_sizes, int n_in,
                              void* d_out, int out_size) {
    const float* x  = (const float*)d_in[0];
    const float* Wg = (const float*)d_in[1];
    const float* W1 = (const float*)d_in[2];
    const float* b1 = (const float*)d_in[3];
    const float* W2 = (const float*)d_in[4];
    const float* b2 = (const float*)d_in[5];
    float* out = (float*)d_out;

    u16 *xh, *w1h, *w2h, *hh;
    float *gbuf, *ybuf;
    cudaGetSymbolAddress((void**)&xh, g_xh);
    cudaGetSymbolAddress((void**)&w1h, g_w1h);
    cudaGetSymbolAddress((void**)&w2h, g_w2h);
    cudaGetSymbolAddress((void**)&hh, g_hh);
    cudaGetSymbolAddress((void**)&gbuf, g_gate);
    cudaGetSymbolAddress((void**)&ybuf, g_y);

    cudaFuncSetAttribute(mma_gemm<0>, cudaFuncAttributeMaxDynamicSharedMemorySize, SM_BYTES);
    cudaFuncSetAttribute(mma_gemm<1>, cudaFuncAttributeMaxDynamicSharedMemorySize, SM_BYTES);

    gate_kernel<<<T_TOK / 8, 256>>>(x, Wg, gbuf);

    size_t n4x = (size_t)T_TOK * HID / 4;
    xcvt_kernel<<<(unsigned)((n4x + 255) / 256), 256>>>(x, xh, n4x);
    tcvt_kernel<<<dim3(INTER / 32, HID / 64, NEXP), dim3(32, 8)>>>(W1, w1h, HID, INTER);
    tcvt_kernel<<<dim3(HID / 32, INTER / 64, NEXP), dim3(32, 8)>>>(W2, w2h, INTER, HID);

    // GEMM1 all experts: M=T, N=INTER, K=HID
    mma_gemm<0><<<dim3(INTER / 128, T_TOK / 128, NEXP), 128, SM_BYTES>>>(
        xh, 0, w1h, b1, nullptr, hh, (size_t)T_TOK * INTER, HID);

    // GEMM2 all experts: M=T, N=HID, K=INTER
    mma_gemm<1><<<dim3(HID / 128, T_TOK / 128, NEXP), 128, SM_BYTES>>>(
        hh, (size_t)T_TOK * INTER, w2h, b2, ybuf, nullptr,
        (size_t)T_TOK * HID, INTER);

    // out = sum_e gate[t,e] * y[e]
    size_t n4o = (size_t)T_TOK * HID / 4;
    reduce_kernel<<<(unsigned)((n4o + 255) / 256), 256>>>(ybuf, gbuf, out);
}